// round 13
// baseline (speedup 1.0000x reference)
#include <cuda_runtime.h>
#include <cuda_fp16.h>
#include <mma.h>

#define NN   100000
#define DD   128
#define PP   64
#define EE   3200000
#define EPTN 5000000
#define EPSI 0.1f
#define INVN (1.0f/100000.0f)
#define BV   (1.0f/64.0f)
#define SCAN_BLOCKS 98   // ceil(100000/1024)
#define SINK_BLOCKS 592  // one full wave: 148 SMs x 4 blocks
#define KSC   16384.0f
#define NNPAD (NN + 64)  // pad rows so last 64-row tile reads in-bounds

using namespace nvcuda::wmma;

// -------- scratch (device globals; no dynamic allocation allowed) ----------
__device__ float g_deg[NN];
__device__ float g_dis[NN];
__device__ __align__(16) __half g_xh[NN*DD];        // fp16 x for agg gathers
__device__ __align__(16) __half g_xsh[(size_t)NNPAD*DD];  // fp16 x_struct (GEMM A)
__device__ __align__(16) __half g_pnh[PP*DD];       // fp16 normalized prompts (GEMM B)
__device__ __align__(16) __half g_Kh[(size_t)NN*PP];
__device__ __align__(16) __half g_sh[(size_t)NN*PP];  // s = 10*(cos-1)  (C = -s/10)
__device__ float g_t[21*PP];
__device__ __align__(16) __half g_xfh[NN*DD];
__device__ unsigned int g_wmax;
__device__ float g_loss;
// CSR scratch
__device__ int   g_rowcnt[NN];
__device__ int   g_rowstart[NN+1];
__device__ int   g_cursor[NN];
__device__ int2  g_csr[EE];
__device__ int   g_bsum[SCAN_BLOCKS];
__device__ unsigned int g_barcnt, g_barS;

__device__ __forceinline__ float warp_sum(float v) {
    v += __shfl_xor_sync(0xffffffffu, v, 16);
    v += __shfl_xor_sync(0xffffffffu, v, 8);
    v += __shfl_xor_sync(0xffffffffu, v, 4);
    v += __shfl_xor_sync(0xffffffffu, v, 2);
    v += __shfl_xor_sync(0xffffffffu, v, 1);
    return v;
}

// KSC * exp(s) via FMA pipe only (no MUFU). s in [-20, ~0].
__device__ __forceinline__ float fexp_ksc(float s) {
    float t = s * 1.4426950408889634f;
    float n = rintf(t);
    float f = t - n;
    float u = f * 0.6931471805599453f;
    float p = 1.f + u * (1.f + u * (0.5f + u * (0.16666666667f + u * 0.04166666667f)));
    int e = ((int)n + 141) << 23;
    return __int_as_float(e) * p;
}

// ---------------------------------------------------------------------------
// fused: init scalars/arrays + x->fp16 convert + prompt normalize (fp16 out)
__global__ void k_pre(const float* __restrict__ x, const float* __restrict__ pt,
                      float* loss_slot) {
    int i = blockIdx.x * blockDim.x + threadIdx.x;
    if (i < NN * DD / 4) {
        float4 v = ((const float4*)x)[i];
        __half2 h0 = __floats2half2_rn(v.x, v.y);
        __half2 h1 = __floats2half2_rn(v.z, v.w);
        uint2 p;
        p.x = *(unsigned int*)&h0;
        p.y = *(unsigned int*)&h1;
        ((uint2*)g_xh)[i] = p;
    }
    if (i < NN) { g_deg[i] = 0.f; g_rowcnt[i] = 0; }
    if (i < 21*PP) g_t[i] = 0.f;
    if (i == 0) {
        g_wmax = 0u; g_barcnt = 0u; g_barS = 0u; g_loss = 0.f; *loss_slot = 0.f;
    }
    if (i < PP * 32) {   // warp per prompt (warp-aligned range)
        int p = i >> 5, lane = i & 31;
        float4 v = *(const float4*)(pt + (size_t)p * DD + lane * 4);
        float ss = warp_sum(v.x*v.x + v.y*v.y + v.z*v.z + v.w*v.w);
        float inv = 1.f / fmaxf(sqrtf(ss), 1e-12f);
        __half2 h0 = __floats2half2_rn(v.x * inv, v.y * inv);
        __half2 h1 = __floats2half2_rn(v.z * inv, v.w * inv);
        uint2 pk;
        pk.x = *(unsigned int*)&h0;
        pk.y = *(unsigned int*)&h1;
        *(uint2*)(g_pnh + (size_t)p * DD + lane * 4) = pk;
    }
}

// degree of col (float) + count of row (int) in one pass
__global__ void k_deg(const int* __restrict__ ei) {
    int e = blockIdx.x * blockDim.x + threadIdx.x;
    if (e < EE) {
        atomicAdd(&g_deg[ei[EE + e]], 1.0f);
        atomicAdd(&g_rowcnt[ei[e]], 1);
    }
}

// merged scan: dis + per-block scan -> grid barrier -> block offsets + cursor
__global__ void __launch_bounds__(1024) k_scan() {
    __shared__ int wsum[32];
    __shared__ int soff;
    int tid = threadIdx.x, lane = tid & 31, w = tid >> 5;
    int bid = blockIdx.x;
    int i = bid * 1024 + tid;
    if (i < NN) {
        float d = g_deg[i];
        g_dis[i] = (d > 0.f) ? rsqrtf(d) : 0.f;
    }
    int v = (i < NN) ? g_rowcnt[i] : 0;
    int s = v;
#pragma unroll
    for (int off = 1; off < 32; off <<= 1) {
        int n = __shfl_up_sync(0xffffffffu, s, off);
        if (lane >= off) s += n;
    }
    if (lane == 31) wsum[w] = s;
    __syncthreads();
    if (w == 0) {
        int t  = wsum[lane];
        int ts = t;
#pragma unroll
        for (int off = 1; off < 32; off <<= 1) {
            int n = __shfl_up_sync(0xffffffffu, ts, off);
            if (lane >= off) ts += n;
        }
        wsum[lane] = ts - t;
    }
    __syncthreads();
    int excl = wsum[w] + s - v;
    if (tid == 1023) g_bsum[bid] = excl + v;
    __threadfence();
    __syncthreads();
    if (tid == 0) {
        atomicAdd(&g_barS, 1u);
        while (*(volatile unsigned*)&g_barS < (unsigned)SCAN_BLOCKS) { __nanosleep(32); }
    }
    __syncthreads();
    if (tid < 32) {
        int acc = 0;
        for (int j = tid; j < bid; j += 32) acc += __ldcg(&g_bsum[j]);
        acc += __shfl_xor_sync(0xffffffffu, acc, 16);
        acc += __shfl_xor_sync(0xffffffffu, acc, 8);
        acc += __shfl_xor_sync(0xffffffffu, acc, 4);
        acc += __shfl_xor_sync(0xffffffffu, acc, 2);
        acc += __shfl_xor_sync(0xffffffffu, acc, 1);
        if (tid == 0) soff = acc;
    }
    __syncthreads();
    if (i < NN) {
        int vv = excl + soff;
        g_rowstart[i] = vv;
        g_cursor[i]   = vv;
    }
    if (i == 0) g_rowstart[NN] = EE;
}

// scatter edges into CSR: one packed 8B store per edge
__global__ void k_scatter(const int* __restrict__ ei, const float* __restrict__ ew) {
    int e = blockIdx.x * blockDim.x + threadIdx.x;
    if (e >= EE) return;
    int r = ei[e];
    int c = ei[EE + e];
    float nw = g_dis[r] * ew[e] * g_dis[c];
    int pos = atomicAdd(&g_cursor[r], 1);
    g_csr[pos] = make_int2(c, __float_as_int(nw));
}

// warp per row: 8-MLP unrolled fp16 gathers with zero-weight masking;
// fused x_struct + l2norm; OUTPUT fp16 (GEMM A operand)
__global__ void k_aggcsr(const float* __restrict__ x, const float* __restrict__ gamma_p) {
    int tid = threadIdx.x;
    int lane = tid & 31;
    int warpId = (blockIdx.x * blockDim.x + tid) >> 5;
    int nW = (gridDim.x * blockDim.x) >> 5;
    float g = *gamma_p;
    for (int r = warpId; r < NN; r += nW) {
        int s = g_rowstart[r], e = g_rowstart[r + 1];
        float4 accA = make_float4(0.f, 0.f, 0.f, 0.f);
        float4 accB = make_float4(0.f, 0.f, 0.f, 0.f);
        for (int base = s; base < e; base += 32) {
            int j = base + lane;
            int cj = 0; float wj = 0.f;
            if (j < e) { int2 cw = g_csr[j]; cj = cw.x; wj = __int_as_float(cw.y); }
#pragma unroll
            for (int k = 0; k < 32; k += 8) {
                int   c0 = __shfl_sync(0xffffffffu, cj, k);
                int   c1 = __shfl_sync(0xffffffffu, cj, k + 1);
                int   c2 = __shfl_sync(0xffffffffu, cj, k + 2);
                int   c3 = __shfl_sync(0xffffffffu, cj, k + 3);
                int   c4 = __shfl_sync(0xffffffffu, cj, k + 4);
                int   c5 = __shfl_sync(0xffffffffu, cj, k + 5);
                int   c6 = __shfl_sync(0xffffffffu, cj, k + 6);
                int   c7 = __shfl_sync(0xffffffffu, cj, k + 7);
                float w0 = __shfl_sync(0xffffffffu, wj, k);
                float w1 = __shfl_sync(0xffffffffu, wj, k + 1);
                float w2 = __shfl_sync(0xffffffffu, wj, k + 2);
                float w3 = __shfl_sync(0xffffffffu, wj, k + 3);
                float w4 = __shfl_sync(0xffffffffu, wj, k + 4);
                float w5 = __shfl_sync(0xffffffffu, wj, k + 5);
                float w6 = __shfl_sync(0xffffffffu, wj, k + 6);
                float w7 = __shfl_sync(0xffffffffu, wj, k + 7);
                uint2 p0 = *(const uint2*)(g_xh + (size_t)c0 * DD + lane * 4);
                uint2 p1 = *(const uint2*)(g_xh + (size_t)c1 * DD + lane * 4);
                uint2 p2 = *(const uint2*)(g_xh + (size_t)c2 * DD + lane * 4);
                uint2 p3 = *(const uint2*)(g_xh + (size_t)c3 * DD + lane * 4);
                uint2 p4 = *(const uint2*)(g_xh + (size_t)c4 * DD + lane * 4);
                uint2 p5 = *(const uint2*)(g_xh + (size_t)c5 * DD + lane * 4);
                uint2 p6 = *(const uint2*)(g_xh + (size_t)c6 * DD + lane * 4);
                uint2 p7 = *(const uint2*)(g_xh + (size_t)c7 * DD + lane * 4);
                float2 a0 = __half22float2(*(__half2*)&p0.x), b0 = __half22float2(*(__half2*)&p0.y);
                float2 a1 = __half22float2(*(__half2*)&p1.x), b1 = __half22float2(*(__half2*)&p1.y);
                float2 a2 = __half22float2(*(__half2*)&p2.x), b2 = __half22float2(*(__half2*)&p2.y);
                float2 a3 = __half22float2(*(__half2*)&p3.x), b3 = __half22float2(*(__half2*)&p3.y);
                float2 a4 = __half22float2(*(__half2*)&p4.x), b4 = __half22float2(*(__half2*)&p4.y);
                float2 a5 = __half22float2(*(__half2*)&p5.x), b5 = __half22float2(*(__half2*)&p5.y);
                float2 a6 = __half22float2(*(__half2*)&p6.x), b6 = __half22float2(*(__half2*)&p6.y);
                float2 a7 = __half22float2(*(__half2*)&p7.x), b7 = __half22float2(*(__half2*)&p7.y);
                accA.x += w0 * a0.x; accA.y += w0 * a0.y; accA.z += w0 * b0.x; accA.w += w0 * b0.y;
                accB.x += w1 * a1.x; accB.y += w1 * a1.y; accB.z += w1 * b1.x; accB.w += w1 * b1.y;
                accA.x += w2 * a2.x; accA.y += w2 * a2.y; accA.z += w2 * b2.x; accA.w += w2 * b2.y;
                accB.x += w3 * a3.x; accB.y += w3 * a3.y; accB.z += w3 * b3.x; accB.w += w3 * b3.y;
                accA.x += w4 * a4.x; accA.y += w4 * a4.y; accA.z += w4 * b4.x; accA.w += w4 * b4.y;
                accB.x += w5 * a5.x; accB.y += w5 * a5.y; accB.z += w5 * b5.x; accB.w += w5 * b5.y;
                accA.x += w6 * a6.x; accA.y += w6 * a6.y; accA.z += w6 * b6.x; accA.w += w6 * b6.y;
                accB.x += w7 * a7.x; accB.y += w7 * a7.y; accB.z += w7 * b7.x; accB.w += w7 * b7.y;
            }
        }
        float4 acc = make_float4(accA.x + accB.x, accA.y + accB.y,
                                 accA.z + accB.z, accA.w + accB.w);
        float4 xv = *(const float4*)(x + (size_t)r * DD + lane * 4);
        float4 sv;
        sv.x = (1.f - g) * xv.x + g * acc.x;
        sv.y = (1.f - g) * xv.y + g * acc.y;
        sv.z = (1.f - g) * xv.z + g * acc.z;
        sv.w = (1.f - g) * xv.w + g * acc.w;
        float ss = warp_sum(sv.x*sv.x + sv.y*sv.y + sv.z*sv.z + sv.w*sv.w);
        float inv = 1.f / fmaxf(sqrtf(ss), 1e-12f);
        __half2 h0 = __floats2half2_rn(sv.x * inv, sv.y * inv);
        __half2 h1 = __floats2half2_rn(sv.z * inv, sv.w * inv);
        uint2 pk;
        pk.x = *(unsigned int*)&h0;
        pk.y = *(unsigned int*)&h1;
        *(uint2*)(g_xsh + (size_t)r * DD + lane * 4) = pk;
    }
}

// kbuild via tensor cores (unchanged from R12 winner)
__global__ void __launch_bounds__(128) k_kbuild() {
    __shared__ float c_sh[4][16][72];
    int tid = threadIdx.x;
    int warp = tid >> 5, lane = tid & 31;
    int rowBase = blockIdx.x * 64 + warp * 16;

    fragment<accumulator, 16, 16, 16, float> cf[4];
#pragma unroll
    for (int n = 0; n < 4; n++) fill_fragment(cf[n], 0.f);
#pragma unroll
    for (int k = 0; k < 8; k++) {
        fragment<matrix_a, 16, 16, 16, __half, row_major> af;
        load_matrix_sync(af, g_xsh + (size_t)rowBase * DD + k * 16, DD);
#pragma unroll
        for (int n = 0; n < 4; n++) {
            fragment<matrix_b, 16, 16, 16, __half, col_major> bf;
            load_matrix_sync(bf, g_pnh + (size_t)(n * 16) * DD + k * 16, DD);
            mma_sync(cf[n], af, bf, cf[n]);
        }
    }
#pragma unroll
    for (int n = 0; n < 4; n++)
        store_matrix_sync(&c_sh[warp][0][n * 16], cf[n], 72, mem_row_major);
    __syncwarp();

    int rloc = lane >> 1;
    int gr = rowBase + rloc;
    int cb = (lane & 1) << 5;
    float* crow = &c_sh[warp][rloc][cb];
    bool ok = (gr < NN);
#pragma unroll
    for (int cc = 0; cc < 32; cc += 4) {
        float s0 = 10.f * (crow[cc]     - 1.f);
        float s1 = 10.f * (crow[cc + 1] - 1.f);
        float s2 = 10.f * (crow[cc + 2] - 1.f);
        float s3 = 10.f * (crow[cc + 3] - 1.f);
        float k0 = ok ? fexp_ksc(s0) : 0.f;
        float k1 = ok ? fexp_ksc(s1) : 0.f;
        float k2 = ok ? fexp_ksc(s2) : 0.f;
        float k3 = ok ? fexp_ksc(s3) : 0.f;
        __half2 h01 = __floats2half2_rn(k0, k1);
        __half2 h23 = __floats2half2_rn(k2, k3);
        float2 f01 = __half22float2(h01);
        float2 f23 = __half22float2(h23);
        crow[cc]     = f01.x;
        crow[cc + 1] = f01.y;
        crow[cc + 2] = f23.x;
        crow[cc + 3] = f23.y;
        if (ok) {
            uint2 pk;
            pk.x = *(unsigned int*)&h01;
            pk.y = *(unsigned int*)&h23;
            *(uint2*)(g_Kh + (size_t)gr * PP + cb + cc) = pk;
            __half2 g01 = __floats2half2_rn(s0, s1);
            __half2 g23 = __floats2half2_rn(s2, s3);
            uint2 ps;
            ps.x = *(unsigned int*)&g01;
            ps.y = *(unsigned int*)&g23;
            *(uint2*)(g_sh + (size_t)gr * PP + cb + cc) = ps;
        }
    }
    __syncthreads();
    if (tid < PP) {
        float sum = 0.f;
#pragma unroll
        for (int w2 = 0; w2 < 4; w2++)
#pragma unroll
            for (int r2 = 0; r2 < 16; r2++) sum += c_sh[w2][r2][tid];
        atomicAdd(&g_t[tid], sum * INVN);
    }
}

// all 19 Sinkhorn iterations in ONE persistent kernel (1 wave, software barrier)
__global__ void __launch_bounds__(256) k_sinkall() {
    __shared__ float v_sh[PP];
    __shared__ float tacc[PP];
    int tid = threadIdx.x, lane = tid & 31;
    int warpId = (blockIdx.x * 256 + tid) >> 5;
    const int nW = (SINK_BLOCKS * 256) >> 5;

    for (int iter = 1; iter <= 19; iter++) {
        if (tid < PP) {
            v_sh[tid] = BV / (__ldcg(&g_t[(iter - 1) * PP + tid]) + 1e-30f);
            tacc[tid] = 0.f;
        }
        __syncthreads();
        float v0 = v_sh[2 * lane], v1 = v_sh[2 * lane + 1];
        float a0 = 0.f, a1 = 0.f;
        for (int r0 = warpId * 4; r0 < NN; r0 += nW * 4) {
            float2 k2[4]; float s[4];
#pragma unroll
            for (int i = 0; i < 4; i++) {
                __half2 h = *(const __half2*)(g_Kh + (size_t)(r0 + i) * PP + 2 * lane);
                k2[i] = __half22float2(h);
            }
#pragma unroll
            for (int i = 0; i < 4; i++) s[i] = k2[i].x * v0 + k2[i].y * v1;
#pragma unroll
            for (int i = 0; i < 4; i++) s[i] = warp_sum(s[i]);
#pragma unroll
            for (int i = 0; i < 4; i++) {
                float u = INVN / (s[i] + 1e-30f);
                a0 += k2[i].x * u;
                a1 += k2[i].y * u;
            }
        }
        atomicAdd(&tacc[2 * lane],     a0);
        atomicAdd(&tacc[2 * lane + 1], a1);
        __syncthreads();
        if (tid < PP) atomicAdd(&g_t[iter * PP + tid], tacc[tid]);
        __threadfence();
        __syncthreads();
        if (tid == 0) {
            atomicAdd(&g_barcnt, 1u);
            unsigned target = (unsigned)iter * gridDim.x;
            while (*(volatile unsigned*)&g_barcnt < target) { __nanosleep(64); }
        }
        __syncthreads();
    }
}

// epilogue with tensor-core GEMM. Block = 128 thr (4 warps), 64 rows.
// Dynamic smem layout: pt_sh fp16 [64][128] @0 (16KB);
//   T_sh fp16 [64][72] @16384 (9216B); pm fp32 [4][16][132] @25600 (33792B).
__global__ void __launch_bounds__(128) k_epi(const float* __restrict__ x,
                                             const float* __restrict__ pt,
                                             const float* __restrict__ alpha_p) {
    extern __shared__ char smem[];
    __half* pt_sh = (__half*)smem;                       // [64][128]
    __half* T_sh  = (__half*)(smem + 16384);             // [64][72]
    float*  pm    = (float*)(smem + 25600);              // [4][16][132]
    __shared__ float v_sh[PP];

    int tid = threadIdx.x;
    int warp = tid >> 5, lane = tid & 31;
    int rowBase = blockIdx.x * 64;
    float* out_x = (float*)0;  // set below via param trick? no — pass via pt? keep param list

    // load raw prompt tokens as fp16
    for (int i = tid; i < PP * DD / 4; i += 128) {
        float4 v = ((const float4*)pt)[i];
        __half2 h0 = __floats2half2_rn(v.x, v.y);
        __half2 h1 = __floats2half2_rn(v.z, v.w);
        uint2 pk;
        pk.x = *(unsigned int*)&h0;
        pk.y = *(unsigned int*)&h1;
        ((uint2*)pt_sh)[i] = pk;
    }
    if (tid < PP) v_sh[tid] = BV / (g_t[19 * PP + tid] + 1e-30f);
    __syncthreads();

    float v0 = v_sh[2 * lane], v1 = v_sh[2 * lane + 1];
    float alpha = *alpha_p;
    float lossAcc = 0.f;

    // phase 1: T (scaled by N) for this warp's 16 rows -> T_sh fp16
#pragma unroll
    for (int rr = 0; rr < 16; rr++) {
        int r = rowBase + warp * 16 + rr;
        float T0 = 0.f, T1 = 0.f;
        if (r < NN) {
            __half2 h = *(const __half2*)(g_Kh + (size_t)r * PP + 2 * lane);
            float2 k2 = __half22float2(h);
            __half2 hs = *(const __half2*)(g_sh + (size_t)r * PP + 2 * lane);
            float2 s2 = __half22float2(hs);
            float s = warp_sum(k2.x * v0 + k2.y * v1);
            float u = INVN / (s + 1e-30f);
            T0 = u * k2.x * v0;
            T1 = u * k2.y * v1;
            lossAcc += T0 * (-0.1f * s2.x) + T1 * (-0.1f * s2.y);
        }
        __half2 nt = __floats2half2_rn(T0 * (float)NN, T1 * (float)NN);
        *(__half2*)&T_sh[(warp * 16 + rr) * 72 + 2 * lane] = nt;
    }
    __syncwarp();

    // phase 2: pm = NT @ pt via HMMA (A 16x64 from T_sh, B 64x128 from pt_sh)
    {
        fragment<accumulator, 16, 16, 16, float> cf[8];
#pragma unroll
        for (int n = 0; n < 8; n++) fill_fragment(cf[n], 0.f);
#pragma unroll
        for (int k = 0; k < 4; k++) {
            fragment<matrix_a, 16, 16, 16, __half, row_major> af;
            load_matrix_sync(af, &T_sh[(warp * 16) * 72 + k * 16], 72);
#pragma unroll
            for (int n = 0; n < 8; n++) {
                fragment<matrix_b, 16, 16, 16, __half, row_major> bf;
                load_matrix_sync(bf, &pt_sh[(k * 16) * DD + n * 16], DD);
                mma_sync(cf[n], af, bf, cf[n]);
            }
        }
#pragma unroll
        for (int n = 0; n < 8; n++)
            store_matrix_sync(&pm[(warp * 16) * 132 + n * 16], cf[n], 132, mem_row_major);
    }
    __syncwarp();

    // phase 3: o = x + alpha*pm; row l2-norm over 128 cols (2 lanes/row);
    // write out_x fp32 + xf fp16. lane -> row lane>>1, col half lane&1.
    // NOTE: out_x passed via pt pointer arithmetic is wrong; use global param below.
    // (out pointer provided through separate kernel parameter)
    // -- implemented in k_epi wrapper below --
    // store o into pm (overwrite) for second pass
    {
        int rloc = lane >> 1;
        int r = rowBase + warp * 16 + rloc;
        int cb = (lane & 1) * 64;
        float* prow = &pm[(warp * 16 + rloc) * 132 + cb];
        if (r < NN) {
            const float* xrow = x + (size_t)r * DD + cb;
            float ssq = 0.f;
#pragma unroll
            for (int c = 0; c < 64; c += 4) {
                float4 xv = *(const float4*)(xrow + c);
                float4 o;
                o.x = xv.x + alpha * prow[c];
                o.y = xv.y + alpha * prow[c + 1];
                o.z = xv.z + alpha * prow[c + 2];
                o.w = xv.w + alpha * prow[c + 3];
                prow[c] = o.x; prow[c + 1] = o.y; prow[c + 2] = o.z; prow[c + 3] = o.w;
                ssq += o.x*o.x + o.y*o.y + o.z*o.z + o.w*o.w;
            }
            ssq += __shfl_xor_sync(0xffffffffu, ssq, 1);
            float inv = 1.f / fmaxf(sqrtf(ssq), 1e-12f);
            // write fp16 xf
#pragma unroll
            for (int c = 0; c < 64; c += 4) {
                __half2 h0 = __floats2half2_rn(prow[c] * inv,     prow[c + 1] * inv);
                __half2 h1 = __floats2half2_rn(prow[c + 2] * inv, prow[c + 3] * inv);
                uint2 pk;
                pk.x = *(unsigned int*)&h0;
                pk.y = *(unsigned int*)&h1;
                *(uint2*)(g_xfh + (size_t)r * DD + cb + c) = pk;
            }
        } else {
            __shfl_xor_sync(0xffffffffu, 0.f, 1);   // keep shuffle uniform
        }
    }

    lossAcc = warp_sum(lossAcc);
    if (lane == 0) atomicAdd(&g_loss, lossAcc);

    // out_x written by helper pass below (needs out pointer) — done here via
    // __syncwarp + second param; see k_epi_out. To avoid extra kernel, the
    // out pointer is smuggled as constant: we instead write in-phase using
    // the global symbol trick is not available -> out param added: see launch.
    (void)out_x;
}

// writes out_x from pm staged in... NOT USED. out_x is written directly in
// k_epi2 below which takes the out pointer.
__global__ void __launch_bounds__(128) k_epi2(const float* __restrict__ x,
                                              const float* __restrict__ pt,
                                              const float* __restrict__ alpha_p,
                                              float* __restrict__ out_x) {
    extern __shared__ char smem[];
    __half* pt_sh = (__half*)smem;                       // [64][128]
    __half* T_sh  = (__half*)(smem + 16384);             // [64][72]
    float*  pm    = (float*)(smem + 25600);              // [4][16][132]
    __shared__ float v_sh[PP];

    int tid = threadIdx.x;
    int warp = tid >> 5, lane = tid & 31;
    int rowBase = blockIdx.x * 64;

    for (int i = tid; i < PP * DD / 4; i += 128) {
        float4 v = ((const float4*)pt)[i];
        __half2 h0 = __floats2half2_rn(v.x, v.y);
        __half2 h1 = __floats2half2_rn(v.z, v.w);
        uint2 pk;
        pk.x = *(unsigned int*)&h0;
        pk.y = *(unsigned int*)&h1;
        ((uint2*)pt_sh)[i] = pk;
    }
    if (tid < PP) v_sh[tid] = BV / (g_t[19 * PP + tid] + 1e-30f);
    __syncthreads();

    float v0 = v_sh[2 * lane], v1 = v_sh[2 * lane + 1];
    float alpha = *alpha_p;
    float lossAcc = 0.f;

#pragma unroll
    for (int rr = 0; rr < 16; rr++) {
        int r = rowBase + warp * 16 + rr;
        float T0 = 0.f, T1 = 0.f;
        if (r < NN) {
            __half2 h = *(const __half2*)(g_Kh + (size_t)r * PP + 2 * lane);
            float2 k2 = __half22float2(h);
            __half2 hs = *(const __half2*)(g_sh + (size_t)r * PP + 2 * lane);
            float2 s2 = __half22float2(hs);
            float s = warp_sum(k2.x * v0 + k2.y * v1);
            float u = INVN / (s + 1e-30f);
            T0 = u * k2.x * v0;
            T1 = u * k2.y * v1;
            lossAcc += T0 * (-0.1f * s2.x) + T1 * (-0.1f * s2.y);
        }
        __half2 nt = __floats2half2_rn(T0 * (float)NN, T1 * (float)NN);
        *(__half2*)&T_sh[(warp * 16 + rr) * 72 + 2 * lane] = nt;
    }
    __syncwarp();

    {
        fragment<accumulator, 16, 16, 16, float> cf[8];
#pragma unroll
        for (int n = 0; n < 8; n++) fill_fragment(cf[n], 0.f);
#pragma unroll
        for (int k = 0; k < 4; k++) {
            fragment<matrix_a, 16, 16, 16, __half, row_major> af;
            load_matrix_sync(af, &T_sh[(warp * 16) * 72 + k * 16], 72);
#pragma unroll
            for (int n = 0; n < 8; n++) {
                fragment<matrix_b, 16, 16, 16, __half, row_major> bf;
                load_matrix_sync(bf, &pt_sh[(k * 16) * DD + n * 16], DD);
                mma_sync(cf[n], af, bf, cf[n]);
            }
        }
#pragma unroll
        for (int n = 0; n < 8; n++)
            store_matrix_sync(&pm[(warp * 16) * 132 + n * 16], cf[n], 132, mem_row_major);
    }
    __syncwarp();

    {
        int rloc = lane >> 1;
        int r = rowBase + warp * 16 + rloc;
        int cb = (lane & 1) * 64;
        float* prow = &pm[(warp * 16 + rloc) * 132 + cb];
        float ssq = 0.f;
        if (r < NN) {
            const float* xrow = x + (size_t)r * DD + cb;
            float* orow = out_x + (size_t)r * DD + cb;
#pragma unroll
            for (int c = 0; c < 64; c += 4) {
                float4 xv = *(const float4*)(xrow + c);
                float4 o;
                o.x = xv.x + alpha * prow[c];
                o.y = xv.y + alpha * prow[c + 1];
                o.z = xv.z + alpha * prow[c + 2];
                o.w = xv.w + alpha * prow[c + 3];
                *(float4*)(orow + c) = o;
                prow[c] = o.x; prow[c + 1] = o.y; prow[c + 2] = o.z; prow[c + 3] = o.w;
                ssq += o.x*o.x + o.y*o.y + o.z*o.z + o.w*o.w;
            }
        }
        ssq += __shfl_xor_sync(0xffffffffu, ssq, 1);
        if (r < NN) {
            float inv = 1.f / fmaxf(sqrtf(ssq), 1e-12f);
#pragma unroll
            for (int c = 0; c < 64; c += 4) {
                __half2 h0 = __floats2half2_rn(prow[c] * inv,     prow[c + 1] * inv);
                __half2 h1 = __floats2half2_rn(prow[c + 2] * inv, prow[c + 3] * inv);
                uint2 pk;
                pk.x = *(unsigned int*)&h0;
                pk.y = *(unsigned int*)&h1;
                *(uint2*)(g_xfh + (size_t)r * DD + cb + c) = pk;
            }
        }
    }

    lossAcc = warp_sum(lossAcc);
    if (lane == 0) atomicAdd(&g_loss, lossAcc);
}

// w_e = relu(dot(xf[r], xf[c])); warp per edge, 4 edges in flight, fp16 gathers
__global__ void k_w(const int* __restrict__ ptei, float* __restrict__ w_out) {
    int tid = threadIdx.x;
    int lane = tid & 31;
    int warpId = (blockIdx.x * blockDim.x + tid) >> 5;
    int nW = (gridDim.x * blockDim.x) >> 5;
    float wmax = 0.f;
    for (int base = warpId * 4; base < EPTN; base += nW * 4) {
        int r[4], c[4];
#pragma unroll
        for (int q = 0; q < 4; q++) {
            r[q] = __ldg(&ptei[base + q]);
            c[q] = __ldg(&ptei[EPTN + base + q]);
        }
        float d[4];
#pragma unroll
        for (int q = 0; q < 4; q++) {
            uint2 ap = *(const uint2*)(g_xfh + (size_t)r[q] * DD + lane * 4);
            uint2 bp = *(const uint2*)(g_xfh + (size_t)c[q] * DD + lane * 4);
            float2 a0 = __half22float2(*(__half2*)&ap.x);
            float2 a1 = __half22float2(*(__half2*)&ap.y);
            float2 b0 = __half22float2(*(__half2*)&bp.x);
            float2 b1 = __half22float2(*(__half2*)&bp.y);
            d[q] = a0.x*b0.x + a0.y*b0.y + a1.x*b1.x + a1.y*b1.y;
        }
#pragma unroll
        for (int q = 0; q < 4; q++) {
            d[q] = warp_sum(d[q]);
            d[q] = fmaxf(d[q], 0.f);
            wmax = fmaxf(wmax, d[q]);
        }
        if (lane < 4) w_out[base + lane] = d[lane];
    }
    wmax = fmaxf(wmax, __shfl_xor_sync(0xffffffffu, wmax, 16));
    wmax = fmaxf(wmax, __shfl_xor_sync(0xffffffffu, wmax, 8));
    wmax = fmaxf(wmax, __shfl_xor_sync(0xffffffffu, wmax, 4));
    wmax = fmaxf(wmax, __shfl_xor_sync(0xffffffffu, wmax, 2));
    wmax = fmaxf(wmax, __shfl_xor_sync(0xffffffffu, wmax, 1));
    if (lane == 0) atomicMax(&g_wmax, __float_as_uint(wmax));
}

__global__ void k_wnorm(float* __restrict__ w_out, float* __restrict__ loss_slot) {
    int i = blockIdx.x * blockDim.x + threadIdx.x;
    if (i < EPTN) {
        float sc = 1.f / (__uint_as_float(g_wmax) + 1e-8f);
        w_out[i] *= sc;
    }
    if (i == 0) *loss_slot = g_loss;
}

// ---------------------------------------------------------------------------
extern "C" void kernel_launch(void* const* d_in, const int* in_sizes, int n_in,
                              void* d_out, int out_size) {
    const float* x     = (const float*)d_in[0];
    const int*   ei    = (const int*)  d_in[1];
    const float* ew    = (const float*)d_in[2];
    const int*   ptei  = (const int*)  d_in[3];
    const float* pt    = (const float*)d_in[4];
    const float* alpha = (const float*)d_in[5];
    const float* gamma = (const float*)d_in[6];
    (void)in_sizes; (void)n_in; (void)out_size;

    float* out       = (float*)d_out;
    float* loss_slot = out + (size_t)NN * DD;
    float* w_out     = loss_slot + 1;

    static bool attr_set = false;
    if (!attr_set) {
        cudaFuncSetAttribute(k_epi2, cudaFuncAttributeMaxDynamicSharedMemorySize, 59392);
        attr_set = true;
    }

    k_pre<<<(NN * DD / 4 + 255) / 256, 256>>>(x, pt, loss_slot);
    k_deg<<<(EE + 255) / 256, 256>>>(ei);
    k_scan<<<SCAN_BLOCKS, 1024>>>();
    k_scatter<<<(EE + 255) / 256, 256>>>(ei, ew);
    k_aggcsr<<<1184, 256>>>(x, gamma);
    k_kbuild<<<(NN + 63) / 64, 128>>>();
    k_sinkall<<<SINK_BLOCKS, 256>>>();
    k_epi2<<<(NN + 63) / 64, 128, 59392>>>(x, pt, alpha, out);
    k_w<<<1184, 256>>>(ptei, w_out);
    k_wnorm<<<(EPTN + 255) / 256, 256>>>(w_out, loss_slot);
}

// round 14
// speedup vs baseline: 1.0433x; 1.0433x over previous
#include <cuda_runtime.h>
#include <cuda_fp16.h>
#include <mma.h>

#define NN   100000
#define DD   128
#define PP   64
#define EE   3200000
#define EPTN 5000000
#define EPSI 0.1f
#define INVN (1.0f/100000.0f)
#define BV   (1.0f/64.0f)
#define SCAN_BLOCKS 98   // ceil(100000/1024)
#define SINK_BLOCKS 592  // one full wave: 148 SMs x 4 blocks
#define KSC   16384.0f
#define NNPAD (NN + 64)  // pad rows so last 64-row tile reads in-bounds

using namespace nvcuda::wmma;

// -------- scratch (device globals; no dynamic allocation allowed) ----------
__device__ float g_deg[NN];
__device__ float g_dis[NN];
__device__ __align__(16) __half g_xh[NN*DD];        // fp16 x for agg gathers
__device__ __align__(16) __half g_xsh[(size_t)NNPAD*DD];  // fp16 x_struct (GEMM A)
__device__ __align__(16) __half g_pnh[PP*DD];       // fp16 normalized prompts (GEMM B)
__device__ __align__(16) __half g_Kh[(size_t)NN*PP];
__device__ __align__(16) __half g_sh[(size_t)NN*PP];  // s = 10*(cos-1)  (C = -s/10)
__device__ float g_t[21*PP];
__device__ __align__(16) __half g_xfh[NN*DD];
__device__ unsigned int g_wmax;
__device__ float g_loss;
// CSR scratch
__device__ int   g_rowcnt[NN];
__device__ int   g_rowstart[NN+1];
__device__ int   g_cursor[NN];
__device__ int2  g_csr[EE];
__device__ int   g_bsum[SCAN_BLOCKS];
__device__ unsigned int g_barcnt, g_barS;

__device__ __forceinline__ float warp_sum(float v) {
    v += __shfl_xor_sync(0xffffffffu, v, 16);
    v += __shfl_xor_sync(0xffffffffu, v, 8);
    v += __shfl_xor_sync(0xffffffffu, v, 4);
    v += __shfl_xor_sync(0xffffffffu, v, 2);
    v += __shfl_xor_sync(0xffffffffu, v, 1);
    return v;
}

// KSC * exp(s) via FMA pipe only (no MUFU). s in [-20, ~0].
__device__ __forceinline__ float fexp_ksc(float s) {
    float t = s * 1.4426950408889634f;
    float n = rintf(t);
    float f = t - n;
    float u = f * 0.6931471805599453f;
    float p = 1.f + u * (1.f + u * (0.5f + u * (0.16666666667f + u * 0.04166666667f)));
    int e = ((int)n + 141) << 23;
    return __int_as_float(e) * p;
}

// ---------------------------------------------------------------------------
// fused: init scalars/arrays + x->fp16 convert + prompt normalize (fp16 out)
__global__ void k_pre(const float* __restrict__ x, const float* __restrict__ pt,
                      float* loss_slot) {
    int i = blockIdx.x * blockDim.x + threadIdx.x;
    if (i < NN * DD / 4) {
        float4 v = ((const float4*)x)[i];
        __half2 h0 = __floats2half2_rn(v.x, v.y);
        __half2 h1 = __floats2half2_rn(v.z, v.w);
        uint2 p;
        p.x = *(unsigned int*)&h0;
        p.y = *(unsigned int*)&h1;
        ((uint2*)g_xh)[i] = p;
    }
    if (i < NN) { g_deg[i] = 0.f; g_rowcnt[i] = 0; }
    if (i < 21*PP) g_t[i] = 0.f;
    if (i == 0) {
        g_wmax = 0u; g_barcnt = 0u; g_barS = 0u; g_loss = 0.f; *loss_slot = 0.f;
    }
    if (i < PP * 32) {   // warp per prompt (warp-aligned range)
        int p = i >> 5, lane = i & 31;
        float4 v = *(const float4*)(pt + (size_t)p * DD + lane * 4);
        float ss = warp_sum(v.x*v.x + v.y*v.y + v.z*v.z + v.w*v.w);
        float inv = 1.f / fmaxf(sqrtf(ss), 1e-12f);
        __half2 h0 = __floats2half2_rn(v.x * inv, v.y * inv);
        __half2 h1 = __floats2half2_rn(v.z * inv, v.w * inv);
        uint2 pk;
        pk.x = *(unsigned int*)&h0;
        pk.y = *(unsigned int*)&h1;
        *(uint2*)(g_pnh + (size_t)p * DD + lane * 4) = pk;
    }
}

// degree of col (float) + count of row (int) in one pass
__global__ void k_deg(const int* __restrict__ ei) {
    int e = blockIdx.x * blockDim.x + threadIdx.x;
    if (e < EE) {
        atomicAdd(&g_deg[ei[EE + e]], 1.0f);
        atomicAdd(&g_rowcnt[ei[e]], 1);
    }
}

// merged scan: dis + per-block scan -> grid barrier -> block offsets + cursor
__global__ void __launch_bounds__(1024) k_scan() {
    __shared__ int wsum[32];
    __shared__ int soff;
    int tid = threadIdx.x, lane = tid & 31, w = tid >> 5;
    int bid = blockIdx.x;
    int i = bid * 1024 + tid;
    if (i < NN) {
        float d = g_deg[i];
        g_dis[i] = (d > 0.f) ? rsqrtf(d) : 0.f;
    }
    int v = (i < NN) ? g_rowcnt[i] : 0;
    int s = v;
#pragma unroll
    for (int off = 1; off < 32; off <<= 1) {
        int n = __shfl_up_sync(0xffffffffu, s, off);
        if (lane >= off) s += n;
    }
    if (lane == 31) wsum[w] = s;
    __syncthreads();
    if (w == 0) {
        int t  = wsum[lane];
        int ts = t;
#pragma unroll
        for (int off = 1; off < 32; off <<= 1) {
            int n = __shfl_up_sync(0xffffffffu, ts, off);
            if (lane >= off) ts += n;
        }
        wsum[lane] = ts - t;
    }
    __syncthreads();
    int excl = wsum[w] + s - v;
    if (tid == 1023) g_bsum[bid] = excl + v;
    __threadfence();
    __syncthreads();
    if (tid == 0) {
        atomicAdd(&g_barS, 1u);
        while (*(volatile unsigned*)&g_barS < (unsigned)SCAN_BLOCKS) { __nanosleep(32); }
    }
    __syncthreads();
    if (tid < 32) {
        int acc = 0;
        for (int j = tid; j < bid; j += 32) acc += __ldcg(&g_bsum[j]);
        acc += __shfl_xor_sync(0xffffffffu, acc, 16);
        acc += __shfl_xor_sync(0xffffffffu, acc, 8);
        acc += __shfl_xor_sync(0xffffffffu, acc, 4);
        acc += __shfl_xor_sync(0xffffffffu, acc, 2);
        acc += __shfl_xor_sync(0xffffffffu, acc, 1);
        if (tid == 0) soff = acc;
    }
    __syncthreads();
    if (i < NN) {
        int vv = excl + soff;
        g_rowstart[i] = vv;
        g_cursor[i]   = vv;
    }
    if (i == 0) g_rowstart[NN] = EE;
}

// scatter edges into CSR: one packed 8B store per edge
__global__ void k_scatter(const int* __restrict__ ei, const float* __restrict__ ew) {
    int e = blockIdx.x * blockDim.x + threadIdx.x;
    if (e >= EE) return;
    int r = ei[e];
    int c = ei[EE + e];
    float nw = g_dis[r] * ew[e] * g_dis[c];
    int pos = atomicAdd(&g_cursor[r], 1);
    g_csr[pos] = make_int2(c, __float_as_int(nw));
}

// warp per row: 8-MLP unrolled fp16 gathers with zero-weight masking;
// fused x_struct + l2norm; OUTPUT fp16 (GEMM A operand)
__global__ void k_aggcsr(const float* __restrict__ x, const float* __restrict__ gamma_p) {
    int tid = threadIdx.x;
    int lane = tid & 31;
    int warpId = (blockIdx.x * blockDim.x + tid) >> 5;
    int nW = (gridDim.x * blockDim.x) >> 5;
    float g = *gamma_p;
    for (int r = warpId; r < NN; r += nW) {
        int s = g_rowstart[r], e = g_rowstart[r + 1];
        float4 accA = make_float4(0.f, 0.f, 0.f, 0.f);
        float4 accB = make_float4(0.f, 0.f, 0.f, 0.f);
        for (int base = s; base < e; base += 32) {
            int j = base + lane;
            int cj = 0; float wj = 0.f;
            if (j < e) { int2 cw = g_csr[j]; cj = cw.x; wj = __int_as_float(cw.y); }
#pragma unroll
            for (int k = 0; k < 32; k += 8) {
                int   c0 = __shfl_sync(0xffffffffu, cj, k);
                int   c1 = __shfl_sync(0xffffffffu, cj, k + 1);
                int   c2 = __shfl_sync(0xffffffffu, cj, k + 2);
                int   c3 = __shfl_sync(0xffffffffu, cj, k + 3);
                int   c4 = __shfl_sync(0xffffffffu, cj, k + 4);
                int   c5 = __shfl_sync(0xffffffffu, cj, k + 5);
                int   c6 = __shfl_sync(0xffffffffu, cj, k + 6);
                int   c7 = __shfl_sync(0xffffffffu, cj, k + 7);
                float w0 = __shfl_sync(0xffffffffu, wj, k);
                float w1 = __shfl_sync(0xffffffffu, wj, k + 1);
                float w2 = __shfl_sync(0xffffffffu, wj, k + 2);
                float w3 = __shfl_sync(0xffffffffu, wj, k + 3);
                float w4 = __shfl_sync(0xffffffffu, wj, k + 4);
                float w5 = __shfl_sync(0xffffffffu, wj, k + 5);
                float w6 = __shfl_sync(0xffffffffu, wj, k + 6);
                float w7 = __shfl_sync(0xffffffffu, wj, k + 7);
                uint2 p0 = *(const uint2*)(g_xh + (size_t)c0 * DD + lane * 4);
                uint2 p1 = *(const uint2*)(g_xh + (size_t)c1 * DD + lane * 4);
                uint2 p2 = *(const uint2*)(g_xh + (size_t)c2 * DD + lane * 4);
                uint2 p3 = *(const uint2*)(g_xh + (size_t)c3 * DD + lane * 4);
                uint2 p4 = *(const uint2*)(g_xh + (size_t)c4 * DD + lane * 4);
                uint2 p5 = *(const uint2*)(g_xh + (size_t)c5 * DD + lane * 4);
                uint2 p6 = *(const uint2*)(g_xh + (size_t)c6 * DD + lane * 4);
                uint2 p7 = *(const uint2*)(g_xh + (size_t)c7 * DD + lane * 4);
                float2 a0 = __half22float2(*(__half2*)&p0.x), b0 = __half22float2(*(__half2*)&p0.y);
                float2 a1 = __half22float2(*(__half2*)&p1.x), b1 = __half22float2(*(__half2*)&p1.y);
                float2 a2 = __half22float2(*(__half2*)&p2.x), b2 = __half22float2(*(__half2*)&p2.y);
                float2 a3 = __half22float2(*(__half2*)&p3.x), b3 = __half22float2(*(__half2*)&p3.y);
                float2 a4 = __half22float2(*(__half2*)&p4.x), b4 = __half22float2(*(__half2*)&p4.y);
                float2 a5 = __half22float2(*(__half2*)&p5.x), b5 = __half22float2(*(__half2*)&p5.y);
                float2 a6 = __half22float2(*(__half2*)&p6.x), b6 = __half22float2(*(__half2*)&p6.y);
                float2 a7 = __half22float2(*(__half2*)&p7.x), b7 = __half22float2(*(__half2*)&p7.y);
                accA.x += w0 * a0.x; accA.y += w0 * a0.y; accA.z += w0 * b0.x; accA.w += w0 * b0.y;
                accB.x += w1 * a1.x; accB.y += w1 * a1.y; accB.z += w1 * b1.x; accB.w += w1 * b1.y;
                accA.x += w2 * a2.x; accA.y += w2 * a2.y; accA.z += w2 * b2.x; accA.w += w2 * b2.y;
                accB.x += w3 * a3.x; accB.y += w3 * a3.y; accB.z += w3 * b3.x; accB.w += w3 * b3.y;
                accA.x += w4 * a4.x; accA.y += w4 * a4.y; accA.z += w4 * b4.x; accA.w += w4 * b4.y;
                accB.x += w5 * a5.x; accB.y += w5 * a5.y; accB.z += w5 * b5.x; accB.w += w5 * b5.y;
                accA.x += w6 * a6.x; accA.y += w6 * a6.y; accA.z += w6 * b6.x; accA.w += w6 * b6.y;
                accB.x += w7 * a7.x; accB.y += w7 * a7.y; accB.z += w7 * b7.x; accB.w += w7 * b7.y;
            }
        }
        float4 acc = make_float4(accA.x + accB.x, accA.y + accB.y,
                                 accA.z + accB.z, accA.w + accB.w);
        float4 xv = *(const float4*)(x + (size_t)r * DD + lane * 4);
        float4 sv;
        sv.x = (1.f - g) * xv.x + g * acc.x;
        sv.y = (1.f - g) * xv.y + g * acc.y;
        sv.z = (1.f - g) * xv.z + g * acc.z;
        sv.w = (1.f - g) * xv.w + g * acc.w;
        float ss = warp_sum(sv.x*sv.x + sv.y*sv.y + sv.z*sv.z + sv.w*sv.w);
        float inv = 1.f / fmaxf(sqrtf(ss), 1e-12f);
        __half2 h0 = __floats2half2_rn(sv.x * inv, sv.y * inv);
        __half2 h1 = __floats2half2_rn(sv.z * inv, sv.w * inv);
        uint2 pk;
        pk.x = *(unsigned int*)&h0;
        pk.y = *(unsigned int*)&h1;
        *(uint2*)(g_xsh + (size_t)r * DD + lane * 4) = pk;
    }
}

// kbuild via tensor cores (R12 winner, unchanged)
__global__ void __launch_bounds__(128) k_kbuild() {
    __shared__ float c_sh[4][16][72];
    int tid = threadIdx.x;
    int warp = tid >> 5, lane = tid & 31;
    int rowBase = blockIdx.x * 64 + warp * 16;

    fragment<accumulator, 16, 16, 16, float> cf[4];
#pragma unroll
    for (int n = 0; n < 4; n++) fill_fragment(cf[n], 0.f);
#pragma unroll
    for (int k = 0; k < 8; k++) {
        fragment<matrix_a, 16, 16, 16, __half, row_major> af;
        load_matrix_sync(af, g_xsh + (size_t)rowBase * DD + k * 16, DD);
#pragma unroll
        for (int n = 0; n < 4; n++) {
            fragment<matrix_b, 16, 16, 16, __half, col_major> bf;
            load_matrix_sync(bf, g_pnh + (size_t)(n * 16) * DD + k * 16, DD);
            mma_sync(cf[n], af, bf, cf[n]);
        }
    }
#pragma unroll
    for (int n = 0; n < 4; n++)
        store_matrix_sync(&c_sh[warp][0][n * 16], cf[n], 72, mem_row_major);
    __syncwarp();

    int rloc = lane >> 1;
    int gr = rowBase + rloc;
    int cb = (lane & 1) << 5;
    float* crow = &c_sh[warp][rloc][cb];
    bool ok = (gr < NN);
#pragma unroll
    for (int cc = 0; cc < 32; cc += 4) {
        float s0 = 10.f * (crow[cc]     - 1.f);
        float s1 = 10.f * (crow[cc + 1] - 1.f);
        float s2 = 10.f * (crow[cc + 2] - 1.f);
        float s3 = 10.f * (crow[cc + 3] - 1.f);
        float k0 = ok ? fexp_ksc(s0) : 0.f;
        float k1 = ok ? fexp_ksc(s1) : 0.f;
        float k2 = ok ? fexp_ksc(s2) : 0.f;
        float k3 = ok ? fexp_ksc(s3) : 0.f;
        __half2 h01 = __floats2half2_rn(k0, k1);
        __half2 h23 = __floats2half2_rn(k2, k3);
        float2 f01 = __half22float2(h01);
        float2 f23 = __half22float2(h23);
        crow[cc]     = f01.x;
        crow[cc + 1] = f01.y;
        crow[cc + 2] = f23.x;
        crow[cc + 3] = f23.y;
        if (ok) {
            uint2 pk;
            pk.x = *(unsigned int*)&h01;
            pk.y = *(unsigned int*)&h23;
            *(uint2*)(g_Kh + (size_t)gr * PP + cb + cc) = pk;
            __half2 g01 = __floats2half2_rn(s0, s1);
            __half2 g23 = __floats2half2_rn(s2, s3);
            uint2 ps;
            ps.x = *(unsigned int*)&g01;
            ps.y = *(unsigned int*)&g23;
            *(uint2*)(g_sh + (size_t)gr * PP + cb + cc) = ps;
        }
    }
    __syncthreads();
    if (tid < PP) {
        float sum = 0.f;
#pragma unroll
        for (int w2 = 0; w2 < 4; w2++)
#pragma unroll
            for (int r2 = 0; r2 < 16; r2++) sum += c_sh[w2][r2][tid];
        atomicAdd(&g_t[tid], sum * INVN);
    }
}

// all 19 Sinkhorn iterations in ONE persistent kernel; 8 rows in flight
__global__ void __launch_bounds__(256) k_sinkall() {
    __shared__ float v_sh[PP];
    __shared__ float tacc[PP];
    int tid = threadIdx.x, lane = tid & 31;
    int warpId = (blockIdx.x * 256 + tid) >> 5;
    const int nW = (SINK_BLOCKS * 256) >> 5;

    for (int iter = 1; iter <= 19; iter++) {
        if (tid < PP) {
            v_sh[tid] = BV / (__ldcg(&g_t[(iter - 1) * PP + tid]) + 1e-30f);
            tacc[tid] = 0.f;
        }
        __syncthreads();
        float v0 = v_sh[2 * lane], v1 = v_sh[2 * lane + 1];
        float a0 = 0.f, a1 = 0.f;
        // NN % 8 == 0 and stride nW*8 -> all groups full
        for (int r0 = warpId * 8; r0 < NN; r0 += nW * 8) {
            float2 k2[8]; float s[8];
#pragma unroll
            for (int i = 0; i < 8; i++) {
                __half2 h = *(const __half2*)(g_Kh + (size_t)(r0 + i) * PP + 2 * lane);
                k2[i] = __half22float2(h);
            }
#pragma unroll
            for (int i = 0; i < 8; i++) s[i] = k2[i].x * v0 + k2[i].y * v1;
#pragma unroll
            for (int i = 0; i < 8; i++) s[i] = warp_sum(s[i]);
#pragma unroll
            for (int i = 0; i < 8; i++) {
                float u = INVN / (s[i] + 1e-30f);
                a0 += k2[i].x * u;
                a1 += k2[i].y * u;
            }
        }
        atomicAdd(&tacc[2 * lane],     a0);
        atomicAdd(&tacc[2 * lane + 1], a1);
        __syncthreads();
        if (tid < PP) atomicAdd(&g_t[iter * PP + tid], tacc[tid]);
        __threadfence();
        __syncthreads();
        if (tid == 0) {
            atomicAdd(&g_barcnt, 1u);
            unsigned target = (unsigned)iter * gridDim.x;
            while (*(volatile unsigned*)&g_barcnt < target) { __nanosleep(64); }
        }
        __syncthreads();
    }
}

// epilogue (R12 winner): T*, ot_loss (no log), prompt_message FMA GEMM,
// x_adapted, xf fp16
__global__ void k_epi(const float* __restrict__ x, const float* __restrict__ pt,
                      const float* __restrict__ alpha_p,
                      float* __restrict__ out_x) {
    __shared__ float pt_sh[PP][DD];
    __shared__ float T_sh[4][8][PP];
    __shared__ float v_sh[PP];
    int tid = threadIdx.x;
    for (int i = tid; i < PP * DD / 4; i += blockDim.x)
        ((float4*)&pt_sh[0][0])[i] = ((const float4*)pt)[i];
    if (tid < PP) v_sh[tid] = BV / (g_t[19 * PP + tid] + 1e-30f);
    __syncthreads();

    int lane = tid & 31, w = tid >> 5;
    int warpId = (blockIdx.x * blockDim.x + tid) >> 5;
    int nW = (gridDim.x * blockDim.x) >> 5;
    float v0 = v_sh[2 * lane], v1 = v_sh[2 * lane + 1];
    float scaleA = (*alpha_p) * (float)NN;
    float lossAcc = 0.f;

    for (int base = warpId * 8; base < NN; base += nW * 8) {
#pragma unroll
        for (int rr = 0; rr < 8; rr++) {
            int r = base + rr;
            __half2 h = *(const __half2*)(g_Kh + (size_t)r * PP + 2 * lane);
            float2 k2 = __half22float2(h);
            __half2 hs = *(const __half2*)(g_sh + (size_t)r * PP + 2 * lane);
            float2 s2 = __half22float2(hs);
            float s = warp_sum(k2.x * v0 + k2.y * v1);
            float u = INVN / (s + 1e-30f);
            float T0 = u * k2.x * v0;
            float T1 = u * k2.y * v1;
            lossAcc += T0 * (-0.1f * s2.x) + T1 * (-0.1f * s2.y);
            T_sh[w][rr][2 * lane]     = T0;
            T_sh[w][rr][2 * lane + 1] = T1;
        }
        __syncwarp();
        float4 pm[8];
#pragma unroll
        for (int rr = 0; rr < 8; rr++) pm[rr] = make_float4(0.f, 0.f, 0.f, 0.f);
#pragma unroll 4
        for (int p = 0; p < PP; p++) {
            float4 pv = *(const float4*)&pt_sh[p][lane * 4];
#pragma unroll
            for (int rr = 0; rr < 8; rr++) {
                float tp = T_sh[w][rr][p];
                pm[rr].x += tp * pv.x;
                pm[rr].y += tp * pv.y;
                pm[rr].z += tp * pv.z;
                pm[rr].w += tp * pv.w;
            }
        }
#pragma unroll
        for (int rr = 0; rr < 8; rr++) {
            int r = base + rr;
            float4 xv = *(const float4*)(x + (size_t)r * DD + lane * 4);
            float4 o;
            o.x = xv.x + scaleA * pm[rr].x;
            o.y = xv.y + scaleA * pm[rr].y;
            o.z = xv.z + scaleA * pm[rr].z;
            o.w = xv.w + scaleA * pm[rr].w;
            *(float4*)(out_x + (size_t)r * DD + lane * 4) = o;
            float ss = warp_sum(o.x*o.x + o.y*o.y + o.z*o.z + o.w*o.w);
            float inv = 1.f / fmaxf(sqrtf(ss), 1e-12f);
            __half2 h0 = __floats2half2_rn(o.x * inv, o.y * inv);
            __half2 h1 = __floats2half2_rn(o.z * inv, o.w * inv);
            uint2 packed;
            packed.x = *(unsigned int*)&h0;
            packed.y = *(unsigned int*)&h1;
            *(uint2*)(g_xfh + (size_t)r * DD + lane * 4) = packed;
        }
        __syncwarp();
    }
    lossAcc = warp_sum(lossAcc);
    if (lane == 0) atomicAdd(&g_loss, lossAcc);
}

// w_e = relu(dot(xf[r], xf[c])); warp per edge, 4 edges in flight, fp16 gathers
__global__ void k_w(const int* __restrict__ ptei, float* __restrict__ w_out) {
    int tid = threadIdx.x;
    int lane = tid & 31;
    int warpId = (blockIdx.x * blockDim.x + tid) >> 5;
    int nW = (gridDim.x * blockDim.x) >> 5;
    float wmax = 0.f;
    for (int base = warpId * 4; base < EPTN; base += nW * 4) {
        int r[4], c[4];
#pragma unroll
        for (int q = 0; q < 4; q++) {
            r[q] = __ldg(&ptei[base + q]);
            c[q] = __ldg(&ptei[EPTN + base + q]);
        }
        float d[4];
#pragma unroll
        for (int q = 0; q < 4; q++) {
            uint2 ap = *(const uint2*)(g_xfh + (size_t)r[q] * DD + lane * 4);
            uint2 bp = *(const uint2*)(g_xfh + (size_t)c[q] * DD + lane * 4);
            float2 a0 = __half22float2(*(__half2*)&ap.x);
            float2 a1 = __half22float2(*(__half2*)&ap.y);
            float2 b0 = __half22float2(*(__half2*)&bp.x);
            float2 b1 = __half22float2(*(__half2*)&bp.y);
            d[q] = a0.x*b0.x + a0.y*b0.y + a1.x*b1.x + a1.y*b1.y;
        }
#pragma unroll
        for (int q = 0; q < 4; q++) {
            d[q] = warp_sum(d[q]);
            d[q] = fmaxf(d[q], 0.f);
            wmax = fmaxf(wmax, d[q]);
        }
        if (lane < 4) w_out[base + lane] = d[lane];
    }
    wmax = fmaxf(wmax, __shfl_xor_sync(0xffffffffu, wmax, 16));
    wmax = fmaxf(wmax, __shfl_xor_sync(0xffffffffu, wmax, 8));
    wmax = fmaxf(wmax, __shfl_xor_sync(0xffffffffu, wmax, 4));
    wmax = fmaxf(wmax, __shfl_xor_sync(0xffffffffu, wmax, 2));
    wmax = fmaxf(wmax, __shfl_xor_sync(0xffffffffu, wmax, 1));
    if (lane == 0) atomicMax(&g_wmax, __float_as_uint(wmax));
}

__global__ void k_wnorm(float* __restrict__ w_out, float* __restrict__ loss_slot) {
    int i = blockIdx.x * blockDim.x + threadIdx.x;
    if (i < EPTN) {
        float sc = 1.f / (__uint_as_float(g_wmax) + 1e-8f);
        w_out[i] *= sc;
    }
    if (i == 0) *loss_slot = g_loss;
}

// ---------------------------------------------------------------------------
extern "C" void kernel_launch(void* const* d_in, const int* in_sizes, int n_in,
                              void* d_out, int out_size) {
    const float* x     = (const float*)d_in[0];
    const int*   ei    = (const int*)  d_in[1];
    const float* ew    = (const float*)d_in[2];
    const int*   ptei  = (const int*)  d_in[3];
    const float* pt    = (const float*)d_in[4];
    const float* alpha = (const float*)d_in[5];
    const float* gamma = (const float*)d_in[6];
    (void)in_sizes; (void)n_in; (void)out_size;

    float* out       = (float*)d_out;
    float* loss_slot = out + (size_t)NN * DD;
    float* w_out     = loss_slot + 1;

    k_pre<<<(NN * DD / 4 + 255) / 256, 256>>>(x, pt, loss_slot);
    k_deg<<<(EE + 255) / 256, 256>>>(ei);
    k_scan<<<SCAN_BLOCKS, 1024>>>();
    k_scatter<<<(EE + 255) / 256, 256>>>(ei, ew);
    k_aggcsr<<<1184, 256>>>(x, gamma);
    k_kbuild<<<(NN + 63) / 64, 128>>>();
    k_sinkall<<<SINK_BLOCKS, 256>>>();
    k_epi<<<1184, 128>>>(x, pt, alpha, out);
    k_w<<<1184, 256>>>(ptei, w_out);
    k_wnorm<<<(EPTN + 255) / 256, 256>>>(w_out, loss_slot);
}

// round 15
// speedup vs baseline: 1.0931x; 1.0477x over previous
#include <cuda_runtime.h>
#include <cuda_fp16.h>
#include <mma.h>

#define NN   100000
#define DD   128
#define PP   64
#define EE   3200000
#define EPTN 5000000
#define EPSI 0.1f
#define INVN (1.0f/100000.0f)
#define BV   (1.0f/64.0f)
#define SCAN_BLOCKS 98   // ceil(100000/1024)
#define SINK_BLOCKS 592  // one full wave: 148 SMs x 4 blocks
#define KSC   16384.0f
#define NNPAD (NN + 64)  // pad rows so last 64-row tile reads in-bounds

using namespace nvcuda::wmma;

// -------- scratch (device globals; no dynamic allocation allowed) ----------
__device__ float g_deg[NN];
__device__ float g_dis[NN];
__device__ __align__(16) __half g_xh[NN*DD];        // fp16 x for agg gathers
__device__ __align__(16) __half g_xsh[(size_t)NNPAD*DD];  // fp16 x_struct (GEMM A)
__device__ __align__(16) __half g_pnh[PP*DD];       // fp16 normalized prompts (GEMM B)
__device__ __align__(16) __half g_Kh[(size_t)NN*PP];
__device__ __align__(16) __half g_sh[(size_t)NN*PP];  // s = 10*(cos-1)  (C = -s/10)
__device__ float g_t[21*PP];
__device__ __align__(16) __half g_xfh[NN*DD];
__device__ unsigned int g_wmax;
__device__ float g_loss;
// CSR scratch
__device__ int   g_rowcnt[NN];
__device__ int   g_rowstart[NN+1];
__device__ int   g_cursor[NN];
__device__ int2  g_csr[EE];
__device__ int   g_bsum[SCAN_BLOCKS];
__device__ unsigned int g_barcnt, g_barS;

__device__ __forceinline__ float warp_sum(float v) {
    v += __shfl_xor_sync(0xffffffffu, v, 16);
    v += __shfl_xor_sync(0xffffffffu, v, 8);
    v += __shfl_xor_sync(0xffffffffu, v, 4);
    v += __shfl_xor_sync(0xffffffffu, v, 2);
    v += __shfl_xor_sync(0xffffffffu, v, 1);
    return v;
}

// KSC * exp(s) via FMA pipe only (no MUFU). s in [-20, ~0].
__device__ __forceinline__ float fexp_ksc(float s) {
    float t = s * 1.4426950408889634f;
    float n = rintf(t);
    float f = t - n;
    float u = f * 0.6931471805599453f;
    float p = 1.f + u * (1.f + u * (0.5f + u * (0.16666666667f + u * 0.04166666667f)));
    int e = ((int)n + 141) << 23;
    return __int_as_float(e) * p;
}

// ---------------------------------------------------------------------------
// fused: init scalars/arrays + x->fp16 convert + prompt normalize (fp16 out)
__global__ void k_pre(const float* __restrict__ x, const float* __restrict__ pt,
                      float* loss_slot) {
    int i = blockIdx.x * blockDim.x + threadIdx.x;
    if (i < NN * DD / 4) {
        float4 v = ((const float4*)x)[i];
        __half2 h0 = __floats2half2_rn(v.x, v.y);
        __half2 h1 = __floats2half2_rn(v.z, v.w);
        uint2 p;
        p.x = *(unsigned int*)&h0;
        p.y = *(unsigned int*)&h1;
        ((uint2*)g_xh)[i] = p;
    }
    if (i < NN) { g_deg[i] = 0.f; g_rowcnt[i] = 0; }
    if (i < 21*PP) g_t[i] = 0.f;
    if (i == 0) {
        g_wmax = 0u; g_barcnt = 0u; g_barS = 0u; g_loss = 0.f; *loss_slot = 0.f;
    }
    if (i < PP * 32) {   // warp per prompt (warp-aligned range)
        int p = i >> 5, lane = i & 31;
        float4 v = *(const float4*)(pt + (size_t)p * DD + lane * 4);
        float ss = warp_sum(v.x*v.x + v.y*v.y + v.z*v.z + v.w*v.w);
        float inv = 1.f / fmaxf(sqrtf(ss), 1e-12f);
        __half2 h0 = __floats2half2_rn(v.x * inv, v.y * inv);
        __half2 h1 = __floats2half2_rn(v.z * inv, v.w * inv);
        uint2 pk;
        pk.x = *(unsigned int*)&h0;
        pk.y = *(unsigned int*)&h1;
        *(uint2*)(g_pnh + (size_t)p * DD + lane * 4) = pk;
    }
}

// degree of col (float) + count of row (int) in one pass
__global__ void k_deg(const int* __restrict__ ei) {
    int e = blockIdx.x * blockDim.x + threadIdx.x;
    if (e < EE) {
        atomicAdd(&g_deg[ei[EE + e]], 1.0f);
        atomicAdd(&g_rowcnt[ei[e]], 1);
    }
}

// merged scan: dis + per-block scan -> grid barrier -> block offsets + cursor
__global__ void __launch_bounds__(1024) k_scan() {
    __shared__ int wsum[32];
    __shared__ int soff;
    int tid = threadIdx.x, lane = tid & 31, w = tid >> 5;
    int bid = blockIdx.x;
    int i = bid * 1024 + tid;
    if (i < NN) {
        float d = g_deg[i];
        g_dis[i] = (d > 0.f) ? rsqrtf(d) : 0.f;
    }
    int v = (i < NN) ? g_rowcnt[i] : 0;
    int s = v;
#pragma unroll
    for (int off = 1; off < 32; off <<= 1) {
        int n = __shfl_up_sync(0xffffffffu, s, off);
        if (lane >= off) s += n;
    }
    if (lane == 31) wsum[w] = s;
    __syncthreads();
    if (w == 0) {
        int t  = wsum[lane];
        int ts = t;
#pragma unroll
        for (int off = 1; off < 32; off <<= 1) {
            int n = __shfl_up_sync(0xffffffffu, ts, off);
            if (lane >= off) ts += n;
        }
        wsum[lane] = ts - t;
    }
    __syncthreads();
    int excl = wsum[w] + s - v;
    if (tid == 1023) g_bsum[bid] = excl + v;
    __threadfence();
    __syncthreads();
    if (tid == 0) {
        atomicAdd(&g_barS, 1u);
        while (*(volatile unsigned*)&g_barS < (unsigned)SCAN_BLOCKS) { __nanosleep(32); }
    }
    __syncthreads();
    if (tid < 32) {
        int acc = 0;
        for (int j = tid; j < bid; j += 32) acc += __ldcg(&g_bsum[j]);
        acc += __shfl_xor_sync(0xffffffffu, acc, 16);
        acc += __shfl_xor_sync(0xffffffffu, acc, 8);
        acc += __shfl_xor_sync(0xffffffffu, acc, 4);
        acc += __shfl_xor_sync(0xffffffffu, acc, 2);
        acc += __shfl_xor_sync(0xffffffffu, acc, 1);
        if (tid == 0) soff = acc;
    }
    __syncthreads();
    if (i < NN) {
        int vv = excl + soff;
        g_rowstart[i] = vv;
        g_cursor[i]   = vv;
    }
    if (i == 0) g_rowstart[NN] = EE;
}

// scatter edges into CSR: one packed 8B store per edge
__global__ void k_scatter(const int* __restrict__ ei, const float* __restrict__ ew) {
    int e = blockIdx.x * blockDim.x + threadIdx.x;
    if (e >= EE) return;
    int r = ei[e];
    int c = ei[EE + e];
    float nw = g_dis[r] * ew[e] * g_dis[c];
    int pos = atomicAdd(&g_cursor[r], 1);
    g_csr[pos] = make_int2(c, __float_as_int(nw));
}

// warp per row: 8-MLP unrolled fp16 gathers with zero-weight masking;
// fused x_struct + l2norm; OUTPUT fp16 (GEMM A operand)
__global__ void k_aggcsr(const float* __restrict__ x, const float* __restrict__ gamma_p) {
    int tid = threadIdx.x;
    int lane = tid & 31;
    int warpId = (blockIdx.x * blockDim.x + tid) >> 5;
    int nW = (gridDim.x * blockDim.x) >> 5;
    float g = *gamma_p;
    for (int r = warpId; r < NN; r += nW) {
        int s = g_rowstart[r], e = g_rowstart[r + 1];
        float4 accA = make_float4(0.f, 0.f, 0.f, 0.f);
        float4 accB = make_float4(0.f, 0.f, 0.f, 0.f);
        for (int base = s; base < e; base += 32) {
            int j = base + lane;
            int cj = 0; float wj = 0.f;
            if (j < e) { int2 cw = g_csr[j]; cj = cw.x; wj = __int_as_float(cw.y); }
#pragma unroll
            for (int k = 0; k < 32; k += 8) {
                int   c0 = __shfl_sync(0xffffffffu, cj, k);
                int   c1 = __shfl_sync(0xffffffffu, cj, k + 1);
                int   c2 = __shfl_sync(0xffffffffu, cj, k + 2);
                int   c3 = __shfl_sync(0xffffffffu, cj, k + 3);
                int   c4 = __shfl_sync(0xffffffffu, cj, k + 4);
                int   c5 = __shfl_sync(0xffffffffu, cj, k + 5);
                int   c6 = __shfl_sync(0xffffffffu, cj, k + 6);
                int   c7 = __shfl_sync(0xffffffffu, cj, k + 7);
                float w0 = __shfl_sync(0xffffffffu, wj, k);
                float w1 = __shfl_sync(0xffffffffu, wj, k + 1);
                float w2 = __shfl_sync(0xffffffffu, wj, k + 2);
                float w3 = __shfl_sync(0xffffffffu, wj, k + 3);
                float w4 = __shfl_sync(0xffffffffu, wj, k + 4);
                float w5 = __shfl_sync(0xffffffffu, wj, k + 5);
                float w6 = __shfl_sync(0xffffffffu, wj, k + 6);
                float w7 = __shfl_sync(0xffffffffu, wj, k + 7);
                uint2 p0 = *(const uint2*)(g_xh + (size_t)c0 * DD + lane * 4);
                uint2 p1 = *(const uint2*)(g_xh + (size_t)c1 * DD + lane * 4);
                uint2 p2 = *(const uint2*)(g_xh + (size_t)c2 * DD + lane * 4);
                uint2 p3 = *(const uint2*)(g_xh + (size_t)c3 * DD + lane * 4);
                uint2 p4 = *(const uint2*)(g_xh + (size_t)c4 * DD + lane * 4);
                uint2 p5 = *(const uint2*)(g_xh + (size_t)c5 * DD + lane * 4);
                uint2 p6 = *(const uint2*)(g_xh + (size_t)c6 * DD + lane * 4);
                uint2 p7 = *(const uint2*)(g_xh + (size_t)c7 * DD + lane * 4);
                float2 a0 = __half22float2(*(__half2*)&p0.x), b0 = __half22float2(*(__half2*)&p0.y);
                float2 a1 = __half22float2(*(__half2*)&p1.x), b1 = __half22float2(*(__half2*)&p1.y);
                float2 a2 = __half22float2(*(__half2*)&p2.x), b2 = __half22float2(*(__half2*)&p2.y);
                float2 a3 = __half22float2(*(__half2*)&p3.x), b3 = __half22float2(*(__half2*)&p3.y);
                float2 a4 = __half22float2(*(__half2*)&p4.x), b4 = __half22float2(*(__half2*)&p4.y);
                float2 a5 = __half22float2(*(__half2*)&p5.x), b5 = __half22float2(*(__half2*)&p5.y);
                float2 a6 = __half22float2(*(__half2*)&p6.x), b6 = __half22float2(*(__half2*)&p6.y);
                float2 a7 = __half22float2(*(__half2*)&p7.x), b7 = __half22float2(*(__half2*)&p7.y);
                accA.x += w0 * a0.x; accA.y += w0 * a0.y; accA.z += w0 * b0.x; accA.w += w0 * b0.y;
                accB.x += w1 * a1.x; accB.y += w1 * a1.y; accB.z += w1 * b1.x; accB.w += w1 * b1.y;
                accA.x += w2 * a2.x; accA.y += w2 * a2.y; accA.z += w2 * b2.x; accA.w += w2 * b2.y;
                accB.x += w3 * a3.x; accB.y += w3 * a3.y; accB.z += w3 * b3.x; accB.w += w3 * b3.y;
                accA.x += w4 * a4.x; accA.y += w4 * a4.y; accA.z += w4 * b4.x; accA.w += w4 * b4.y;
                accB.x += w5 * a5.x; accB.y += w5 * a5.y; accB.z += w5 * b5.x; accB.w += w5 * b5.y;
                accA.x += w6 * a6.x; accA.y += w6 * a6.y; accA.z += w6 * b6.x; accA.w += w6 * b6.y;
                accB.x += w7 * a7.x; accB.y += w7 * a7.y; accB.z += w7 * b7.x; accB.w += w7 * b7.y;
            }
        }
        float4 acc = make_float4(accA.x + accB.x, accA.y + accB.y,
                                 accA.z + accB.z, accA.w + accB.w);
        float4 xv = *(const float4*)(x + (size_t)r * DD + lane * 4);
        float4 sv;
        sv.x = (1.f - g) * xv.x + g * acc.x;
        sv.y = (1.f - g) * xv.y + g * acc.y;
        sv.z = (1.f - g) * xv.z + g * acc.z;
        sv.w = (1.f - g) * xv.w + g * acc.w;
        float ss = warp_sum(sv.x*sv.x + sv.y*sv.y + sv.z*sv.z + sv.w*sv.w);
        float inv = 1.f / fmaxf(sqrtf(ss), 1e-12f);
        __half2 h0 = __floats2half2_rn(sv.x * inv, sv.y * inv);
        __half2 h1 = __floats2half2_rn(sv.z * inv, sv.w * inv);
        uint2 pk;
        pk.x = *(unsigned int*)&h0;
        pk.y = *(unsigned int*)&h1;
        *(uint2*)(g_xsh + (size_t)r * DD + lane * 4) = pk;
    }
}

// kbuild via tensor cores (R12 winner, unchanged)
__global__ void __launch_bounds__(128) k_kbuild() {
    __shared__ float c_sh[4][16][72];
    int tid = threadIdx.x;
    int warp = tid >> 5, lane = tid & 31;
    int rowBase = blockIdx.x * 64 + warp * 16;

    fragment<accumulator, 16, 16, 16, float> cf[4];
#pragma unroll
    for (int n = 0; n < 4; n++) fill_fragment(cf[n], 0.f);
#pragma unroll
    for (int k = 0; k < 8; k++) {
        fragment<matrix_a, 16, 16, 16, __half, row_major> af;
        load_matrix_sync(af, g_xsh + (size_t)rowBase * DD + k * 16, DD);
#pragma unroll
        for (int n = 0; n < 4; n++) {
            fragment<matrix_b, 16, 16, 16, __half, col_major> bf;
            load_matrix_sync(bf, g_pnh + (size_t)(n * 16) * DD + k * 16, DD);
            mma_sync(cf[n], af, bf, cf[n]);
        }
    }
#pragma unroll
    for (int n = 0; n < 4; n++)
        store_matrix_sync(&c_sh[warp][0][n * 16], cf[n], 72, mem_row_major);
    __syncwarp();

    int rloc = lane >> 1;
    int gr = rowBase + rloc;
    int cb = (lane & 1) << 5;
    float* crow = &c_sh[warp][rloc][cb];
    bool ok = (gr < NN);
#pragma unroll
    for (int cc = 0; cc < 32; cc += 4) {
        float s0 = 10.f * (crow[cc]     - 1.f);
        float s1 = 10.f * (crow[cc + 1] - 1.f);
        float s2 = 10.f * (crow[cc + 2] - 1.f);
        float s3 = 10.f * (crow[cc + 3] - 1.f);
        float k0 = ok ? fexp_ksc(s0) : 0.f;
        float k1 = ok ? fexp_ksc(s1) : 0.f;
        float k2 = ok ? fexp_ksc(s2) : 0.f;
        float k3 = ok ? fexp_ksc(s3) : 0.f;
        __half2 h01 = __floats2half2_rn(k0, k1);
        __half2 h23 = __floats2half2_rn(k2, k3);
        float2 f01 = __half22float2(h01);
        float2 f23 = __half22float2(h23);
        crow[cc]     = f01.x;
        crow[cc + 1] = f01.y;
        crow[cc + 2] = f23.x;
        crow[cc + 3] = f23.y;
        if (ok) {
            uint2 pk;
            pk.x = *(unsigned int*)&h01;
            pk.y = *(unsigned int*)&h23;
            *(uint2*)(g_Kh + (size_t)gr * PP + cb + cc) = pk;
            __half2 g01 = __floats2half2_rn(s0, s1);
            __half2 g23 = __floats2half2_rn(s2, s3);
            uint2 ps;
            ps.x = *(unsigned int*)&g01;
            ps.y = *(unsigned int*)&g23;
            *(uint2*)(g_sh + (size_t)gr * PP + cb + cc) = ps;
        }
    }
    __syncthreads();
    if (tid < PP) {
        float sum = 0.f;
#pragma unroll
        for (int w2 = 0; w2 < 4; w2++)
#pragma unroll
            for (int r2 = 0; r2 < 16; r2++) sum += c_sh[w2][r2][tid];
        atomicAdd(&g_t[tid], sum * INVN);
    }
}

// all 19 Sinkhorn iterations in ONE persistent kernel; 8 rows in flight
__global__ void __launch_bounds__(256) k_sinkall() {
    __shared__ float v_sh[PP];
    __shared__ float tacc[PP];
    int tid = threadIdx.x, lane = tid & 31;
    int warpId = (blockIdx.x * 256 + tid) >> 5;
    const int nW = (SINK_BLOCKS * 256) >> 5;

    for (int iter = 1; iter <= 19; iter++) {
        if (tid < PP) {
            v_sh[tid] = BV / (__ldcg(&g_t[(iter - 1) * PP + tid]) + 1e-30f);
            tacc[tid] = 0.f;
        }
        __syncthreads();
        float v0 = v_sh[2 * lane], v1 = v_sh[2 * lane + 1];
        float a0 = 0.f, a1 = 0.f;
        for (int r0 = warpId * 8; r0 < NN; r0 += nW * 8) {
            float2 k2[8]; float s[8];
#pragma unroll
            for (int i = 0; i < 8; i++) {
                __half2 h = *(const __half2*)(g_Kh + (size_t)(r0 + i) * PP + 2 * lane);
                k2[i] = __half22float2(h);
            }
#pragma unroll
            for (int i = 0; i < 8; i++) s[i] = k2[i].x * v0 + k2[i].y * v1;
#pragma unroll
            for (int i = 0; i < 8; i++) s[i] = warp_sum(s[i]);
#pragma unroll
            for (int i = 0; i < 8; i++) {
                float u = INVN / (s[i] + 1e-30f);
                a0 += k2[i].x * u;
                a1 += k2[i].y * u;
            }
        }
        atomicAdd(&tacc[2 * lane],     a0);
        atomicAdd(&tacc[2 * lane + 1], a1);
        __syncthreads();
        if (tid < PP) atomicAdd(&g_t[iter * PP + tid], tacc[tid]);
        __threadfence();
        __syncthreads();
        if (tid == 0) {
            atomicAdd(&g_barcnt, 1u);
            unsigned target = (unsigned)iter * gridDim.x;
            while (*(volatile unsigned*)&g_barcnt < target) { __nanosleep(64); }
        }
        __syncthreads();
    }
}

// epilogue: T*, ot_loss (no log); prompt_message via HFMA2 (packed fp16 math);
// x_adapted fp32 out, xf fp16
__global__ void k_epi(const float* __restrict__ x, const float* __restrict__ pt,
                      const float* __restrict__ alpha_p,
                      float* __restrict__ out_x) {
    __shared__ __half2 pt_sh2[PP * DD / 2];   // 16 KB: pt_sh2[p*64 + c] = (pt[p][2c], pt[p][2c+1])
    __shared__ __half  T_sh[4][8][PP];        // 4 KB: N*T in fp16
    __shared__ float   v_sh[PP];
    int tid = threadIdx.x;
    for (int i = tid; i < PP * DD / 4; i += blockDim.x) {
        float4 v = ((const float4*)pt)[i];
        __half2 h0 = __floats2half2_rn(v.x, v.y);
        __half2 h1 = __floats2half2_rn(v.z, v.w);
        uint2 pk;
        pk.x = *(unsigned int*)&h0;
        pk.y = *(unsigned int*)&h1;
        ((uint2*)pt_sh2)[i] = pk;
    }
    if (tid < PP) v_sh[tid] = BV / (g_t[19 * PP + tid] + 1e-30f);
    __syncthreads();

    int lane = tid & 31, w = tid >> 5;
    int warpId = (blockIdx.x * blockDim.x + tid) >> 5;
    int nW = (gridDim.x * blockDim.x) >> 5;
    float v0 = v_sh[2 * lane], v1 = v_sh[2 * lane + 1];
    float alpha = *alpha_p;
    float lossAcc = 0.f;

    for (int base = warpId * 8; base < NN; base += nW * 8) {
#pragma unroll
        for (int rr = 0; rr < 8; rr++) {
            int r = base + rr;
            __half2 h = *(const __half2*)(g_Kh + (size_t)r * PP + 2 * lane);
            float2 k2 = __half22float2(h);
            __half2 hs = *(const __half2*)(g_sh + (size_t)r * PP + 2 * lane);
            float2 s2 = __half22float2(hs);
            float s = warp_sum(k2.x * v0 + k2.y * v1);
            float u = INVN / (s + 1e-30f);
            float T0 = u * k2.x * v0;
            float T1 = u * k2.y * v1;
            lossAcc += T0 * (-0.1f * s2.x) + T1 * (-0.1f * s2.y);
            *(__half2*)&T_sh[w][rr][2 * lane] =
                __floats2half2_rn(T0 * (float)NN, T1 * (float)NN);
        }
        __syncwarp();
        // pm = (N*T) @ pt in packed fp16: each lane owns cols [4*lane, 4*lane+4)
        __half2 pm0[8], pm1[8];
#pragma unroll
        for (int rr = 0; rr < 8; rr++) {
            pm0[rr] = __floats2half2_rn(0.f, 0.f);
            pm1[rr] = __floats2half2_rn(0.f, 0.f);
        }
#pragma unroll 4
        for (int p = 0; p < PP; p++) {
            __half2 pv0 = pt_sh2[p * (DD / 2) + lane * 2];
            __half2 pv1 = pt_sh2[p * (DD / 2) + lane * 2 + 1];
#pragma unroll
            for (int rr = 0; rr < 8; rr++) {
                __half2 tt = __half2half2(T_sh[w][rr][p]);
                pm0[rr] = __hfma2(tt, pv0, pm0[rr]);
                pm1[rr] = __hfma2(tt, pv1, pm1[rr]);
            }
        }
#pragma unroll
        for (int rr = 0; rr < 8; rr++) {
            int r = base + rr;
            float2 pa = __half22float2(pm0[rr]);
            float2 pb = __half22float2(pm1[rr]);
            float4 xv = *(const float4*)(x + (size_t)r * DD + lane * 4);
            float4 o;
            o.x = xv.x + alpha * pa.x;
            o.y = xv.y + alpha * pa.y;
            o.z = xv.z + alpha * pb.x;
            o.w = xv.w + alpha * pb.y;
            *(float4*)(out_x + (size_t)r * DD + lane * 4) = o;
            float ss = warp_sum(o.x*o.x + o.y*o.y + o.z*o.z + o.w*o.w);
            float inv = 1.f / fmaxf(sqrtf(ss), 1e-12f);
            __half2 h0 = __floats2half2_rn(o.x * inv, o.y * inv);
            __half2 h1 = __floats2half2_rn(o.z * inv, o.w * inv);
            uint2 packed;
            packed.x = *(unsigned int*)&h0;
            packed.y = *(unsigned int*)&h1;
            *(uint2*)(g_xfh + (size_t)r * DD + lane * 4) = packed;
        }
        __syncwarp();
    }
    lossAcc = warp_sum(lossAcc);
    if (lane == 0) atomicAdd(&g_loss, lossAcc);
}

// w_e = relu(dot(xf[r], xf[c])); warp per edge, 4 edges in flight, fp16 gathers
__global__ void k_w(const int* __restrict__ ptei, float* __restrict__ w_out) {
    int tid = threadIdx.x;
    int lane = tid & 31;
    int warpId = (blockIdx.x * blockDim.x + tid) >> 5;
    int nW = (gridDim.x * blockDim.x) >> 5;
    float wmax = 0.f;
    for (int base = warpId * 4; base < EPTN; base += nW * 4) {
        int r[4], c[4];
#pragma unroll
        for (int q = 0; q < 4; q++) {
            r[q] = __ldg(&ptei[base + q]);
            c[q] = __ldg(&ptei[EPTN + base + q]);
        }
        float d[4];
#pragma unroll
        for (int q = 0; q < 4; q++) {
            uint2 ap = *(const uint2*)(g_xfh + (size_t)r[q] * DD + lane * 4);
            uint2 bp = *(const uint2*)(g_xfh + (size_t)c[q] * DD + lane * 4);
            float2 a0 = __half22float2(*(__half2*)&ap.x);
            float2 a1 = __half22float2(*(__half2*)&ap.y);
            float2 b0 = __half22float2(*(__half2*)&bp.x);
            float2 b1 = __half22float2(*(__half2*)&bp.y);
            d[q] = a0.x*b0.x + a0.y*b0.y + a1.x*b1.x + a1.y*b1.y;
        }
#pragma unroll
        for (int q = 0; q < 4; q++) {
            d[q] = warp_sum(d[q]);
            d[q] = fmaxf(d[q], 0.f);
            wmax = fmaxf(wmax, d[q]);
        }
        if (lane < 4) w_out[base + lane] = d[lane];
    }
    wmax = fmaxf(wmax, __shfl_xor_sync(0xffffffffu, wmax, 16));
    wmax = fmaxf(wmax, __shfl_xor_sync(0xffffffffu, wmax, 8));
    wmax = fmaxf(wmax, __shfl_xor_sync(0xffffffffu, wmax, 4));
    wmax = fmaxf(wmax, __shfl_xor_sync(0xffffffffu, wmax, 2));
    wmax = fmaxf(wmax, __shfl_xor_sync(0xffffffffu, wmax, 1));
    if (lane == 0) atomicMax(&g_wmax, __float_as_uint(wmax));
}

__global__ void k_wnorm(float* __restrict__ w_out, float* __restrict__ loss_slot) {
    int i = blockIdx.x * blockDim.x + threadIdx.x;
    if (i < EPTN) {
        float sc = 1.f / (__uint_as_float(g_wmax) + 1e-8f);
        w_out[i] *= sc;
    }
    if (i == 0) *loss_slot = g_loss;
}

// ---------------------------------------------------------------------------
extern "C" void kernel_launch(void* const* d_in, const int* in_sizes, int n_in,
                              void* d_out, int out_size) {
    const float* x     = (const float*)d_in[0];
    const int*   ei    = (const int*)  d_in[1];
    const float* ew    = (const float*)d_in[2];
    const int*   ptei  = (const int*)  d_in[3];
    const float* pt    = (const float*)d_in[4];
    const float* alpha = (const float*)d_in[5];
    const float* gamma = (const float*)d_in[6];
    (void)in_sizes; (void)n_in; (void)out_size;

    float* out       = (float*)d_out;
    float* loss_slot = out + (size_t)NN * DD;
    float* w_out     = loss_slot + 1;

    k_pre<<<(NN * DD / 4 + 255) / 256, 256>>>(x, pt, loss_slot);
    k_deg<<<(EE + 255) / 256, 256>>>(ei);
    k_scan<<<SCAN_BLOCKS, 1024>>>();
    k_scatter<<<(EE + 255) / 256, 256>>>(ei, ew);
    k_aggcsr<<<1184, 256>>>(x, gamma);
    k_kbuild<<<(NN + 63) / 64, 128>>>();
    k_sinkall<<<SINK_BLOCKS, 256>>>();
    k_epi<<<1184, 128>>>(x, pt, alpha, out);
    k_w<<<1184, 256>>>(ptei, w_out);
    k_wnorm<<<(EPTN + 255) / 256, 256>>>(w_out, loss_slot);
}

// round 16
// speedup vs baseline: 1.1123x; 1.0176x over previous
#include <cuda_runtime.h>
#include <cuda_fp16.h>
#include <mma.h>

#define NN   100000
#define DD   128
#define PP   64
#define EE   3200000
#define EPTN 5000000
#define EPSI 0.1f
#define INVN (1.0f/100000.0f)
#define BV   (1.0f/64.0f)
#define SCAN_BLOCKS 98   // ceil(100000/1024)
#define SINK_BLOCKS 592  // one full wave: 148 SMs x 4 blocks
#define KSC   16384.0f
#define NNPAD (NN + 64)  // pad rows so last 64-row tile reads in-bounds

using namespace nvcuda::wmma;

// -------- scratch (device globals; no dynamic allocation allowed) ----------
__device__ float g_deg[NN];
__device__ float g_dis[NN];
__device__ __align__(16) __half g_xh[NN*DD];        // fp16 x for agg gathers
__device__ __align__(16) __half g_xsh[(size_t)NNPAD*DD];  // fp16 x_struct (GEMM A)
__device__ __align__(16) __half g_pnh[PP*DD];       // fp16 normalized prompts (GEMM B)
__device__ __align__(16) __half g_Kh[(size_t)NN*PP];
__device__ __align__(16) __half g_sh[(size_t)NN*PP];  // s = 10*(cos-1)  (C = -s/10)
__device__ float g_t[21*PP];
__device__ __align__(16) __half g_xfh[NN*DD];
__device__ unsigned int g_wmax;
__device__ float g_loss;
// CSR scratch
__device__ int   g_rowcnt[NN];
__device__ int   g_rowstart[NN+1];
__device__ int   g_cursor[NN];
__device__ int2  g_csr[EE];
__device__ int   g_bsum[SCAN_BLOCKS];
__device__ unsigned int g_barcnt, g_barS;

__device__ __forceinline__ float warp_sum(float v) {
    v += __shfl_xor_sync(0xffffffffu, v, 16);
    v += __shfl_xor_sync(0xffffffffu, v, 8);
    v += __shfl_xor_sync(0xffffffffu, v, 4);
    v += __shfl_xor_sync(0xffffffffu, v, 2);
    v += __shfl_xor_sync(0xffffffffu, v, 1);
    return v;
}

// KSC * exp(s) via FMA pipe only (no MUFU). s in [-20, ~0].
__device__ __forceinline__ float fexp_ksc(float s) {
    float t = s * 1.4426950408889634f;
    float n = rintf(t);
    float f = t - n;
    float u = f * 0.6931471805599453f;
    float p = 1.f + u * (1.f + u * (0.5f + u * (0.16666666667f + u * 0.04166666667f)));
    int e = ((int)n + 141) << 23;
    return __int_as_float(e) * p;
}

// ---------------------------------------------------------------------------
// fused: init scalars/arrays + x->fp16 convert + prompt normalize (fp16 out)
__global__ void k_pre(const float* __restrict__ x, const float* __restrict__ pt,
                      float* loss_slot) {
    int i = blockIdx.x * blockDim.x + threadIdx.x;
    if (i < NN * DD / 4) {
        float4 v = ((const float4*)x)[i];
        __half2 h0 = __floats2half2_rn(v.x, v.y);
        __half2 h1 = __floats2half2_rn(v.z, v.w);
        uint2 p;
        p.x = *(unsigned int*)&h0;
        p.y = *(unsigned int*)&h1;
        ((uint2*)g_xh)[i] = p;
    }
    if (i < NN) { g_deg[i] = 0.f; g_rowcnt[i] = 0; }
    if (i < 21*PP) g_t[i] = 0.f;
    if (i == 0) {
        g_wmax = 0u; g_barcnt = 0u; g_barS = 0u; g_loss = 0.f; *loss_slot = 0.f;
    }
    if (i < PP * 32) {   // warp per prompt (warp-aligned range)
        int p = i >> 5, lane = i & 31;
        float4 v = *(const float4*)(pt + (size_t)p * DD + lane * 4);
        float ss = warp_sum(v.x*v.x + v.y*v.y + v.z*v.z + v.w*v.w);
        float inv = 1.f / fmaxf(sqrtf(ss), 1e-12f);
        __half2 h0 = __floats2half2_rn(v.x * inv, v.y * inv);
        __half2 h1 = __floats2half2_rn(v.z * inv, v.w * inv);
        uint2 pk;
        pk.x = *(unsigned int*)&h0;
        pk.y = *(unsigned int*)&h1;
        *(uint2*)(g_pnh + (size_t)p * DD + lane * 4) = pk;
    }
}

// degree of col (float) + count of row (int) in one pass
__global__ void k_deg(const int* __restrict__ ei) {
    int e = blockIdx.x * blockDim.x + threadIdx.x;
    if (e < EE) {
        atomicAdd(&g_deg[ei[EE + e]], 1.0f);
        atomicAdd(&g_rowcnt[ei[e]], 1);
    }
}

// merged scan: dis + per-block scan -> grid barrier -> block offsets + cursor
__global__ void __launch_bounds__(1024) k_scan() {
    __shared__ int wsum[32];
    __shared__ int soff;
    int tid = threadIdx.x, lane = tid & 31, w = tid >> 5;
    int bid = blockIdx.x;
    int i = bid * 1024 + tid;
    if (i < NN) {
        float d = g_deg[i];
        g_dis[i] = (d > 0.f) ? rsqrtf(d) : 0.f;
    }
    int v = (i < NN) ? g_rowcnt[i] : 0;
    int s = v;
#pragma unroll
    for (int off = 1; off < 32; off <<= 1) {
        int n = __shfl_up_sync(0xffffffffu, s, off);
        if (lane >= off) s += n;
    }
    if (lane == 31) wsum[w] = s;
    __syncthreads();
    if (w == 0) {
        int t  = wsum[lane];
        int ts = t;
#pragma unroll
        for (int off = 1; off < 32; off <<= 1) {
            int n = __shfl_up_sync(0xffffffffu, ts, off);
            if (lane >= off) ts += n;
        }
        wsum[lane] = ts - t;
    }
    __syncthreads();
    int excl = wsum[w] + s - v;
    if (tid == 1023) g_bsum[bid] = excl + v;
    __threadfence();
    __syncthreads();
    if (tid == 0) {
        atomicAdd(&g_barS, 1u);
        while (*(volatile unsigned*)&g_barS < (unsigned)SCAN_BLOCKS) { __nanosleep(32); }
    }
    __syncthreads();
    if (tid < 32) {
        int acc = 0;
        for (int j = tid; j < bid; j += 32) acc += __ldcg(&g_bsum[j]);
        acc += __shfl_xor_sync(0xffffffffu, acc, 16);
        acc += __shfl_xor_sync(0xffffffffu, acc, 8);
        acc += __shfl_xor_sync(0xffffffffu, acc, 4);
        acc += __shfl_xor_sync(0xffffffffu, acc, 2);
        acc += __shfl_xor_sync(0xffffffffu, acc, 1);
        if (tid == 0) soff = acc;
    }
    __syncthreads();
    if (i < NN) {
        int vv = excl + soff;
        g_rowstart[i] = vv;
        g_cursor[i]   = vv;
    }
    if (i == 0) g_rowstart[NN] = EE;
}

// scatter edges into CSR: one packed 8B store per edge
__global__ void k_scatter(const int* __restrict__ ei, const float* __restrict__ ew) {
    int e = blockIdx.x * blockDim.x + threadIdx.x;
    if (e >= EE) return;
    int r = ei[e];
    int c = ei[EE + e];
    float nw = g_dis[r] * ew[e] * g_dis[c];
    int pos = atomicAdd(&g_cursor[r], 1);
    g_csr[pos] = make_int2(c, __float_as_int(nw));
}

// warp per row: 8-MLP unrolled fp16 gathers with zero-weight masking;
// fused x_struct + l2norm; OUTPUT fp16 (GEMM A operand)
__global__ void k_aggcsr(const float* __restrict__ x, const float* __restrict__ gamma_p) {
    int tid = threadIdx.x;
    int lane = tid & 31;
    int warpId = (blockIdx.x * blockDim.x + tid) >> 5;
    int nW = (gridDim.x * blockDim.x) >> 5;
    float g = *gamma_p;
    for (int r = warpId; r < NN; r += nW) {
        int s = g_rowstart[r], e = g_rowstart[r + 1];
        float4 accA = make_float4(0.f, 0.f, 0.f, 0.f);
        float4 accB = make_float4(0.f, 0.f, 0.f, 0.f);
        for (int base = s; base < e; base += 32) {
            int j = base + lane;
            int cj = 0; float wj = 0.f;
            if (j < e) { int2 cw = g_csr[j]; cj = cw.x; wj = __int_as_float(cw.y); }
#pragma unroll
            for (int k = 0; k < 32; k += 8) {
                int   c0 = __shfl_sync(0xffffffffu, cj, k);
                int   c1 = __shfl_sync(0xffffffffu, cj, k + 1);
                int   c2 = __shfl_sync(0xffffffffu, cj, k + 2);
                int   c3 = __shfl_sync(0xffffffffu, cj, k + 3);
                int   c4 = __shfl_sync(0xffffffffu, cj, k + 4);
                int   c5 = __shfl_sync(0xffffffffu, cj, k + 5);
                int   c6 = __shfl_sync(0xffffffffu, cj, k + 6);
                int   c7 = __shfl_sync(0xffffffffu, cj, k + 7);
                float w0 = __shfl_sync(0xffffffffu, wj, k);
                float w1 = __shfl_sync(0xffffffffu, wj, k + 1);
                float w2 = __shfl_sync(0xffffffffu, wj, k + 2);
                float w3 = __shfl_sync(0xffffffffu, wj, k + 3);
                float w4 = __shfl_sync(0xffffffffu, wj, k + 4);
                float w5 = __shfl_sync(0xffffffffu, wj, k + 5);
                float w6 = __shfl_sync(0xffffffffu, wj, k + 6);
                float w7 = __shfl_sync(0xffffffffu, wj, k + 7);
                uint2 p0 = *(const uint2*)(g_xh + (size_t)c0 * DD + lane * 4);
                uint2 p1 = *(const uint2*)(g_xh + (size_t)c1 * DD + lane * 4);
                uint2 p2 = *(const uint2*)(g_xh + (size_t)c2 * DD + lane * 4);
                uint2 p3 = *(const uint2*)(g_xh + (size_t)c3 * DD + lane * 4);
                uint2 p4 = *(const uint2*)(g_xh + (size_t)c4 * DD + lane * 4);
                uint2 p5 = *(const uint2*)(g_xh + (size_t)c5 * DD + lane * 4);
                uint2 p6 = *(const uint2*)(g_xh + (size_t)c6 * DD + lane * 4);
                uint2 p7 = *(const uint2*)(g_xh + (size_t)c7 * DD + lane * 4);
                float2 a0 = __half22float2(*(__half2*)&p0.x), b0 = __half22float2(*(__half2*)&p0.y);
                float2 a1 = __half22float2(*(__half2*)&p1.x), b1 = __half22float2(*(__half2*)&p1.y);
                float2 a2 = __half22float2(*(__half2*)&p2.x), b2 = __half22float2(*(__half2*)&p2.y);
                float2 a3 = __half22float2(*(__half2*)&p3.x), b3 = __half22float2(*(__half2*)&p3.y);
                float2 a4 = __half22float2(*(__half2*)&p4.x), b4 = __half22float2(*(__half2*)&p4.y);
                float2 a5 = __half22float2(*(__half2*)&p5.x), b5 = __half22float2(*(__half2*)&p5.y);
                float2 a6 = __half22float2(*(__half2*)&p6.x), b6 = __half22float2(*(__half2*)&p6.y);
                float2 a7 = __half22float2(*(__half2*)&p7.x), b7 = __half22float2(*(__half2*)&p7.y);
                accA.x += w0 * a0.x; accA.y += w0 * a0.y; accA.z += w0 * b0.x; accA.w += w0 * b0.y;
                accB.x += w1 * a1.x; accB.y += w1 * a1.y; accB.z += w1 * b1.x; accB.w += w1 * b1.y;
                accA.x += w2 * a2.x; accA.y += w2 * a2.y; accA.z += w2 * b2.x; accA.w += w2 * b2.y;
                accB.x += w3 * a3.x; accB.y += w3 * a3.y; accB.z += w3 * b3.x; accB.w += w3 * b3.y;
                accA.x += w4 * a4.x; accA.y += w4 * a4.y; accA.z += w4 * b4.x; accA.w += w4 * b4.y;
                accB.x += w5 * a5.x; accB.y += w5 * a5.y; accB.z += w5 * b5.x; accB.w += w5 * b5.y;
                accA.x += w6 * a6.x; accA.y += w6 * a6.y; accA.z += w6 * b6.x; accA.w += w6 * b6.y;
                accB.x += w7 * a7.x; accB.y += w7 * a7.y; accB.z += w7 * b7.x; accB.w += w7 * b7.y;
            }
        }
        float4 acc = make_float4(accA.x + accB.x, accA.y + accB.y,
                                 accA.z + accB.z, accA.w + accB.w);
        float4 xv = *(const float4*)(x + (size_t)r * DD + lane * 4);
        float4 sv;
        sv.x = (1.f - g) * xv.x + g * acc.x;
        sv.y = (1.f - g) * xv.y + g * acc.y;
        sv.z = (1.f - g) * xv.z + g * acc.z;
        sv.w = (1.f - g) * xv.w + g * acc.w;
        float ss = warp_sum(sv.x*sv.x + sv.y*sv.y + sv.z*sv.z + sv.w*sv.w);
        float inv = 1.f / fmaxf(sqrtf(ss), 1e-12f);
        __half2 h0 = __floats2half2_rn(sv.x * inv, sv.y * inv);
        __half2 h1 = __floats2half2_rn(sv.z * inv, sv.w * inv);
        uint2 pk;
        pk.x = *(unsigned int*)&h0;
        pk.y = *(unsigned int*)&h1;
        *(uint2*)(g_xsh + (size_t)r * DD + lane * 4) = pk;
    }
}

// kbuild via tensor cores (R12 winner, unchanged)
__global__ void __launch_bounds__(128) k_kbuild() {
    __shared__ float c_sh[4][16][72];
    int tid = threadIdx.x;
    int warp = tid >> 5, lane = tid & 31;
    int rowBase = blockIdx.x * 64 + warp * 16;

    fragment<accumulator, 16, 16, 16, float> cf[4];
#pragma unroll
    for (int n = 0; n < 4; n++) fill_fragment(cf[n], 0.f);
#pragma unroll
    for (int k = 0; k < 8; k++) {
        fragment<matrix_a, 16, 16, 16, __half, row_major> af;
        load_matrix_sync(af, g_xsh + (size_t)rowBase * DD + k * 16, DD);
#pragma unroll
        for (int n = 0; n < 4; n++) {
            fragment<matrix_b, 16, 16, 16, __half, col_major> bf;
            load_matrix_sync(bf, g_pnh + (size_t)(n * 16) * DD + k * 16, DD);
            mma_sync(cf[n], af, bf, cf[n]);
        }
    }
#pragma unroll
    for (int n = 0; n < 4; n++)
        store_matrix_sync(&c_sh[warp][0][n * 16], cf[n], 72, mem_row_major);
    __syncwarp();

    int rloc = lane >> 1;
    int gr = rowBase + rloc;
    int cb = (lane & 1) << 5;
    float* crow = &c_sh[warp][rloc][cb];
    bool ok = (gr < NN);
#pragma unroll
    for (int cc = 0; cc < 32; cc += 4) {
        float s0 = 10.f * (crow[cc]     - 1.f);
        float s1 = 10.f * (crow[cc + 1] - 1.f);
        float s2 = 10.f * (crow[cc + 2] - 1.f);
        float s3 = 10.f * (crow[cc + 3] - 1.f);
        float k0 = ok ? fexp_ksc(s0) : 0.f;
        float k1 = ok ? fexp_ksc(s1) : 0.f;
        float k2 = ok ? fexp_ksc(s2) : 0.f;
        float k3 = ok ? fexp_ksc(s3) : 0.f;
        __half2 h01 = __floats2half2_rn(k0, k1);
        __half2 h23 = __floats2half2_rn(k2, k3);
        float2 f01 = __half22float2(h01);
        float2 f23 = __half22float2(h23);
        crow[cc]     = f01.x;
        crow[cc + 1] = f01.y;
        crow[cc + 2] = f23.x;
        crow[cc + 3] = f23.y;
        if (ok) {
            uint2 pk;
            pk.x = *(unsigned int*)&h01;
            pk.y = *(unsigned int*)&h23;
            *(uint2*)(g_Kh + (size_t)gr * PP + cb + cc) = pk;
            __half2 g01 = __floats2half2_rn(s0, s1);
            __half2 g23 = __floats2half2_rn(s2, s3);
            uint2 ps;
            ps.x = *(unsigned int*)&g01;
            ps.y = *(unsigned int*)&g23;
            *(uint2*)(g_sh + (size_t)gr * PP + cb + cc) = ps;
        }
    }
    __syncthreads();
    if (tid < PP) {
        float sum = 0.f;
#pragma unroll
        for (int w2 = 0; w2 < 4; w2++)
#pragma unroll
            for (int r2 = 0; r2 < 16; r2++) sum += c_sh[w2][r2][tid];
        atomicAdd(&g_t[tid], sum * INVN);
    }
}

// all 19 Sinkhorn iterations in ONE persistent kernel; 8 rows in flight
__global__ void __launch_bounds__(256) k_sinkall() {
    __shared__ float v_sh[PP];
    __shared__ float tacc[PP];
    int tid = threadIdx.x, lane = tid & 31;
    int warpId = (blockIdx.x * 256 + tid) >> 5;
    const int nW = (SINK_BLOCKS * 256) >> 5;

    for (int iter = 1; iter <= 19; iter++) {
        if (tid < PP) {
            v_sh[tid] = BV / (__ldcg(&g_t[(iter - 1) * PP + tid]) + 1e-30f);
            tacc[tid] = 0.f;
        }
        __syncthreads();
        float v0 = v_sh[2 * lane], v1 = v_sh[2 * lane + 1];
        float a0 = 0.f, a1 = 0.f;
        for (int r0 = warpId * 8; r0 < NN; r0 += nW * 8) {
            float2 k2[8]; float s[8];
#pragma unroll
            for (int i = 0; i < 8; i++) {
                __half2 h = *(const __half2*)(g_Kh + (size_t)(r0 + i) * PP + 2 * lane);
                k2[i] = __half22float2(h);
            }
#pragma unroll
            for (int i = 0; i < 8; i++) s[i] = k2[i].x * v0 + k2[i].y * v1;
#pragma unroll
            for (int i = 0; i < 8; i++) s[i] = warp_sum(s[i]);
#pragma unroll
            for (int i = 0; i < 8; i++) {
                float u = INVN / (s[i] + 1e-30f);
                a0 += k2[i].x * u;
                a1 += k2[i].y * u;
            }
        }
        atomicAdd(&tacc[2 * lane],     a0);
        atomicAdd(&tacc[2 * lane + 1], a1);
        __syncthreads();
        if (tid < PP) atomicAdd(&g_t[iter * PP + tid], tacc[tid]);
        __threadfence();
        __syncthreads();
        if (tid == 0) {
            atomicAdd(&g_barcnt, 1u);
            unsigned target = (unsigned)iter * gridDim.x;
            while (*(volatile unsigned*)&g_barcnt < target) { __nanosleep(64); }
        }
        __syncthreads();
    }
}

// epilogue: T*, ot_loss (no log); prompt_message via HFMA2 (packed fp16 math);
// x_adapted fp32 out, xf fp16
__global__ void k_epi(const float* __restrict__ x, const float* __restrict__ pt,
                      const float* __restrict__ alpha_p,
                      float* __restrict__ out_x) {
    __shared__ __half2 pt_sh2[PP * DD / 2];
    __shared__ __half  T_sh[4][8][PP];
    __shared__ float   v_sh[PP];
    int tid = threadIdx.x;
    for (int i = tid; i < PP * DD / 4; i += blockDim.x) {
        float4 v = ((const float4*)pt)[i];
        __half2 h0 = __floats2half2_rn(v.x, v.y);
        __half2 h1 = __floats2half2_rn(v.z, v.w);
        uint2 pk;
        pk.x = *(unsigned int*)&h0;
        pk.y = *(unsigned int*)&h1;
        ((uint2*)pt_sh2)[i] = pk;
    }
    if (tid < PP) v_sh[tid] = BV / (g_t[19 * PP + tid] + 1e-30f);
    __syncthreads();

    int lane = tid & 31, w = tid >> 5;
    int warpId = (blockIdx.x * blockDim.x + tid) >> 5;
    int nW = (gridDim.x * blockDim.x) >> 5;
    float v0 = v_sh[2 * lane], v1 = v_sh[2 * lane + 1];
    float alpha = *alpha_p;
    float lossAcc = 0.f;

    for (int base = warpId * 8; base < NN; base += nW * 8) {
#pragma unroll
        for (int rr = 0; rr < 8; rr++) {
            int r = base + rr;
            __half2 h = *(const __half2*)(g_Kh + (size_t)r * PP + 2 * lane);
            float2 k2 = __half22float2(h);
            __half2 hs = *(const __half2*)(g_sh + (size_t)r * PP + 2 * lane);
            float2 s2 = __half22float2(hs);
            float s = warp_sum(k2.x * v0 + k2.y * v1);
            float u = INVN / (s + 1e-30f);
            float T0 = u * k2.x * v0;
            float T1 = u * k2.y * v1;
            lossAcc += T0 * (-0.1f * s2.x) + T1 * (-0.1f * s2.y);
            *(__half2*)&T_sh[w][rr][2 * lane] =
                __floats2half2_rn(T0 * (float)NN, T1 * (float)NN);
        }
        __syncwarp();
        __half2 pm0[8], pm1[8];
#pragma unroll
        for (int rr = 0; rr < 8; rr++) {
            pm0[rr] = __floats2half2_rn(0.f, 0.f);
            pm1[rr] = __floats2half2_rn(0.f, 0.f);
        }
#pragma unroll 4
        for (int p = 0; p < PP; p++) {
            __half2 pv0 = pt_sh2[p * (DD / 2) + lane * 2];
            __half2 pv1 = pt_sh2[p * (DD / 2) + lane * 2 + 1];
#pragma unroll
            for (int rr = 0; rr < 8; rr++) {
                __half2 tt = __half2half2(T_sh[w][rr][p]);
                pm0[rr] = __hfma2(tt, pv0, pm0[rr]);
                pm1[rr] = __hfma2(tt, pv1, pm1[rr]);
            }
        }
#pragma unroll
        for (int rr = 0; rr < 8; rr++) {
            int r = base + rr;
            float2 pa = __half22float2(pm0[rr]);
            float2 pb = __half22float2(pm1[rr]);
            float4 xv = *(const float4*)(x + (size_t)r * DD + lane * 4);
            float4 o;
            o.x = xv.x + alpha * pa.x;
            o.y = xv.y + alpha * pa.y;
            o.z = xv.z + alpha * pb.x;
            o.w = xv.w + alpha * pb.y;
            *(float4*)(out_x + (size_t)r * DD + lane * 4) = o;
            float ss = warp_sum(o.x*o.x + o.y*o.y + o.z*o.z + o.w*o.w);
            float inv = 1.f / fmaxf(sqrtf(ss), 1e-12f);
            __half2 h0 = __floats2half2_rn(o.x * inv, o.y * inv);
            __half2 h1 = __floats2half2_rn(o.z * inv, o.w * inv);
            uint2 packed;
            packed.x = *(unsigned int*)&h0;
            packed.y = *(unsigned int*)&h1;
            *(uint2*)(g_xfh + (size_t)r * DD + lane * 4) = packed;
        }
        __syncwarp();
    }
    lossAcc = warp_sum(lossAcc);
    if (lane == 0) atomicAdd(&g_loss, lossAcc);
}

// w_e = relu(dot(xf[r], xf[c])); warp per edge, 8 edges in flight, fp16 gathers
__global__ void k_w(const int* __restrict__ ptei, float* __restrict__ w_out) {
    int tid = threadIdx.x;
    int lane = tid & 31;
    int warpId = (blockIdx.x * blockDim.x + tid) >> 5;
    int nW = (gridDim.x * blockDim.x) >> 5;
    float wmax = 0.f;
    // EPTN % 8 == 0 and warp stride multiple of 8 -> all groups full
    for (int base = warpId * 8; base < EPTN; base += nW * 8) {
        int r[8], c[8];
#pragma unroll
        for (int q = 0; q < 8; q++) {
            r[q] = __ldg(&ptei[base + q]);
            c[q] = __ldg(&ptei[EPTN + base + q]);
        }
        float d[8];
#pragma unroll
        for (int q = 0; q < 8; q++) {
            uint2 ap = *(const uint2*)(g_xfh + (size_t)r[q] * DD + lane * 4);
            uint2 bp = *(const uint2*)(g_xfh + (size_t)c[q] * DD + lane * 4);
            float2 a0 = __half22float2(*(__half2*)&ap.x);
            float2 a1 = __half22float2(*(__half2*)&ap.y);
            float2 b0 = __half22float2(*(__half2*)&bp.x);
            float2 b1 = __half22float2(*(__half2*)&bp.y);
            d[q] = a0.x*b0.x + a0.y*b0.y + a1.x*b1.x + a1.y*b1.y;
        }
#pragma unroll
        for (int q = 0; q < 8; q++) {
            d[q] = warp_sum(d[q]);
            d[q] = fmaxf(d[q], 0.f);
            wmax = fmaxf(wmax, d[q]);
        }
        if (lane < 8) w_out[base + lane] = d[lane];
    }
    wmax = fmaxf(wmax, __shfl_xor_sync(0xffffffffu, wmax, 16));
    wmax = fmaxf(wmax, __shfl_xor_sync(0xffffffffu, wmax, 8));
    wmax = fmaxf(wmax, __shfl_xor_sync(0xffffffffu, wmax, 4));
    wmax = fmaxf(wmax, __shfl_xor_sync(0xffffffffu, wmax, 2));
    wmax = fmaxf(wmax, __shfl_xor_sync(0xffffffffu, wmax, 1));
    if (lane == 0) atomicMax(&g_wmax, __float_as_uint(wmax));
}

__global__ void k_wnorm(float* __restrict__ w_out, float* __restrict__ loss_slot) {
    int i = blockIdx.x * blockDim.x + threadIdx.x;
    if (i < EPTN) {
        float sc = 1.f / (__uint_as_float(g_wmax) + 1e-8f);
        w_out[i] *= sc;
    }
    if (i == 0) *loss_slot = g_loss;
}

// ---------------------------------------------------------------------------
extern "C" void kernel_launch(void* const* d_in, const int* in_sizes, int n_in,
                              void* d_out, int out_size) {
    const float* x     = (const float*)d_in[0];
    const int*   ei    = (const int*)  d_in[1];
    const float* ew    = (const float*)d_in[2];
    const int*   ptei  = (const int*)  d_in[3];
    const float* pt    = (const float*)d_in[4];
    const float* alpha = (const float*)d_in[5];
    const float* gamma = (const float*)d_in[6];
    (void)in_sizes; (void)n_in; (void)out_size;

    float* out       = (float*)d_out;
    float* loss_slot = out + (size_t)NN * DD;
    float* w_out     = loss_slot + 1;

    k_pre<<<(NN * DD / 4 + 255) / 256, 256>>>(x, pt, loss_slot);
    k_deg<<<(EE + 255) / 256, 256>>>(ei);
    k_scan<<<SCAN_BLOCKS, 1024>>>();
    k_scatter<<<(EE + 255) / 256, 256>>>(ei, ew);
    k_aggcsr<<<1184, 256>>>(x, gamma);
    k_kbuild<<<(NN + 63) / 64, 128>>>();
    k_sinkall<<<SINK_BLOCKS, 256>>>();
    k_epi<<<1184, 128>>>(x, pt, alpha, out);
    k_w<<<1184, 256>>>(ptei, w_out);
    k_wnorm<<<(EPTN + 255) / 256, 256>>>(w_out, loss_slot);
}